// round 6
// baseline (speedup 1.0000x reference)
#include <cuda_runtime.h>
#include <math.h>
#include <stdint.h>

// ---------------- problem constants ----------------
#define NLITS 4000
#define NCLS  8000
#define E     128
#define H1    400
#define H2    200
#define H2P   208          // H2 padded to multiple of 16
#define NG    512          // 4*E LSTM gates
#define TSTEPS 30
#define LIT_STRIDE 512
#define CLS_STRIDE 256
#define VOTE_BLOCKS ((NLITS + 7) / 8)
#define BK 16
#define SP 20              // smem row stride in floats (16 + 4 pad, 80B: conflict-free)
#define SMEM_BYTES (6 * 128 * SP * 4)   // As/Bhs/Bls x double buffer

// ---------------- device scratch (static, BSS zero-init, allocation-free) ----------------
__device__ float g_Lh[NLITS * E], g_Lc[NLITS * E];
__device__ float g_Ch[NCLS * E],  g_Cc[NCLS * E];
__device__ float g_b1L[NLITS * H1], g_b1C[NCLS * H1];
__device__ float g_b2L[NLITS * H2P], g_b2C[NCLS * H2P];   // pad cols stay 0 (never written)
__device__ float g_mlpL[NLITS * E],  g_mlpC[NCLS * E];
__device__ float g_msgL[NLITS * E],  g_msgC[NCLS * E];
__device__ float g_gatesC[NCLS * NG], g_gatesL[NLITS * NG];

// pre-split weights (hi/lo tf32-valued fp32), K padded where needed
__device__ float g_LC1h[H1 * E],   g_LC1l[H1 * E];
__device__ float g_LC2h[H2 * H1],  g_LC2l[H2 * H1];
__device__ float g_LC3h[E * H2P],  g_LC3l[E * H2P];
__device__ float g_CL1h[H1 * E],   g_CL1l[H1 * E];
__device__ float g_CL2h[H2 * H1],  g_CL2l[H2 * H1];
__device__ float g_CL3h[E * H2P],  g_CL3l[E * H2P];
__device__ float g_CWih[NG * E],   g_CWil[NG * E];
__device__ float g_CWhh[NG * E],   g_CWhl[NG * E];
__device__ float g_LWih[NG * E],   g_LWil[NG * E];
__device__ float g_LWhh[NG * E],   g_LWhl[NG * E];
__device__ float g_VW1h[H1 * E],   g_VW1l[H1 * E];
__device__ float g_VW2h[H2 * H1],  g_VW2l[H2 * H1];

__device__ int   g_lit_idx[(size_t)NLITS * LIT_STRIDE];
__device__ int   g_lit_len[NLITS];
__device__ int   g_cls_idx[(size_t)NCLS * CLS_STRIDE];
__device__ int   g_cls_len[NCLS];
__device__ float g_partials[VOTE_BLOCKS];

// ---------------- tf32 split helpers ----------------
__device__ __forceinline__ void split_f32(float v, uint32_t& h, uint32_t& l) {
    asm("cvt.rn.tf32.f32 %0, %1;" : "=r"(h) : "f"(v));
    float r = v - __uint_as_float(h);
    asm("cvt.rn.tf32.f32 %0, %1;" : "=r"(l) : "f"(r));
}

// ---------------- adjacency builders ----------------
__global__ void build_lit_kernel(const float* __restrict__ M) {
    int l = blockIdx.x * (blockDim.x >> 5) + (threadIdx.x >> 5);
    int lane = threadIdx.x & 31;
    if (l >= NLITS) return;
    const float* row = M + (size_t)l * NCLS;
    int cnt = 0;
    for (int c0 = 0; c0 < NCLS; c0 += 32) {
        float v = row[c0 + lane];
        unsigned mask = __ballot_sync(0xffffffffu, v != 0.0f);
        if (v != 0.0f) {
            int pos = cnt + __popc(mask & ((1u << lane) - 1u));
            if (pos < LIT_STRIDE) g_lit_idx[(size_t)l * LIT_STRIDE + pos] = c0 + lane;
        }
        cnt += __popc(mask);
    }
    if (lane == 0) g_lit_len[l] = cnt < LIT_STRIDE ? cnt : LIT_STRIDE;
}

__global__ void build_cls_kernel(const float* __restrict__ M) {
    int c = blockIdx.x * (blockDim.x >> 5) + (threadIdx.x >> 5);
    int lane = threadIdx.x & 31;
    if (c >= NCLS) return;
    int cnt = 0;
    for (int l0 = 0; l0 < NLITS; l0 += 32) {
        float v = M[(size_t)(l0 + lane) * NCLS + c];
        unsigned mask = __ballot_sync(0xffffffffu, v != 0.0f);
        if (v != 0.0f) {
            int pos = cnt + __popc(mask & ((1u << lane) - 1u));
            if (pos < CLS_STRIDE) g_cls_idx[(size_t)c * CLS_STRIDE + pos] = l0 + lane;
        }
        cnt += __popc(mask);
    }
    if (lane == 0) g_cls_len[c] = cnt < CLS_STRIDE ? cnt : CLS_STRIDE;
}

// ---------------- weight splitter (with optional K padding) ----------------
__global__ void split_weight_kernel(const float* __restrict__ in, float* __restrict__ hi,
                                    float* __restrict__ lo, int rows, int K, int KP) {
    int i = blockIdx.x * blockDim.x + threadIdx.x;
    if (i >= rows * KP) return;
    int r = i / KP, k = i - r * KP;
    float v = (k < K) ? in[(size_t)r * K + k] : 0.0f;
    uint32_t h, l;
    split_f32(v, h, l);
    hi[i] = __uint_as_float(h);
    lo[i] = __uint_as_float(l);
}

// ---------------- state init ----------------
__global__ void init_states_kernel(const float* __restrict__ L_init,
                                   const float* __restrict__ C_init) {
    int i = blockIdx.x * blockDim.x + threadIdx.x;
    const int totL = NLITS * E;
    if (i < totL) {
        g_Lh[i] = L_init[i & (E - 1)]; g_Lc[i] = 0.0f;
    } else if (i < totL + NCLS * E) {
        int j = i - totL;
        g_Ch[j] = C_init[j & (E - 1)]; g_Cc[j] = 0.0f;
    }
}

// ---------------- tf32x4 tensor-core GEMM ----------------
// C = act( sum_seg A[seg] @ W[seg]^T + bias ); A:[M,K] fp32 row-major (pitch=K),
// W pre-split into Wh/Wl (tf32-valued fp32, [N,K] row-major). fp32 out.
// A split into (hi,lo) in registers; 4 mma terms: hh + hl + lh + ll.
struct GP {
    const float* A[2];
    const float* Bh[2];
    const float* Bl[2];
    const float* bias;
    float* out;
    int M;
    int nseg;
};

__device__ __forceinline__ unsigned smem_u32(const void* p) {
    return (unsigned)__cvta_generic_to_shared(p);
}

#define LDSM4(R0, R1, R2, R3, ADDR)                                          \
    asm volatile("ldmatrix.sync.aligned.m8n8.x4.shared.b16 {%0,%1,%2,%3}, [%4];" \
                 : "=r"(R0), "=r"(R1), "=r"(R2), "=r"(R3) : "r"(ADDR))

#define MMA_TF32(C, A, B)                                              \
    asm volatile(                                                      \
        "mma.sync.aligned.m16n8k8.row.col.f32.tf32.tf32.f32 "          \
        "{%0,%1,%2,%3}, {%4,%5,%6,%7}, {%8,%9}, {%0,%1,%2,%3};"        \
        : "+f"((C)[0]), "+f"((C)[1]), "+f"((C)[2]), "+f"((C)[3])       \
        : "r"((A)[0]), "r"((A)[1]), "r"((A)[2]), "r"((A)[3]),          \
          "r"((B)[0]), "r"((B)[1]))

template <bool RELU>
__global__ void __launch_bounds__(256) gemm_tf32x4_kernel(GP p0, GP p1, int N, int K, int opitch)
{
    const GP p = (blockIdx.z == 0) ? p0 : p1;
    const int m0 = blockIdx.y * 128;
    if (m0 >= p.M) return;
    const int n0 = blockIdx.x * 128;

    extern __shared__ float sm_[];
    float (*As)[128][SP]  = (float(*)[128][SP])(sm_);
    float (*Bhs)[128][SP] = (float(*)[128][SP])(sm_ + 2 * 128 * SP);
    float (*Bls)[128][SP] = (float(*)[128][SP])(sm_ + 4 * 128 * SP);

    const int tid = threadIdx.x;
    const int lane = tid & 31;
    const int wid = tid >> 5;
    const int wm0 = (wid & 3) * 32;   // 4 warps over M
    const int wn0 = (wid >> 2) * 64;  // 2 warps over N
    const int g = lane >> 2;
    const int q = lane & 3;
    const int sel = lane >> 3;        // ldmatrix sub-matrix select

    const int ntiles = K / BK;
    const int total = ntiles * p.nseg;

    float c[2][8][4];
#pragma unroll
    for (int a = 0; a < 2; a++)
#pragma unroll
        for (int b = 0; b < 8; b++)
#pragma unroll
            for (int d = 0; d < 4; d++) c[a][b][d] = 0.0f;

    float4 va[2], vbh[2], vbl[2];

    auto load_g = [&](int ti) {
        int seg = ti / ntiles;
        int k0 = (ti - seg * ntiles) * BK;
        const float* Ap  = p.A[seg];
        const float* Bph = p.Bh[seg];
        const float* Bpl = p.Bl[seg];
#pragma unroll
        for (int i = 0; i < 2; i++) {
            int idx = tid + i * 256;
            int row = idx >> 2;
            int qq = idx & 3;
            float4 v = make_float4(0.f, 0.f, 0.f, 0.f);
            int gr = m0 + row;
            if (gr < p.M) v = *(const float4*)(Ap + (size_t)gr * K + k0 + qq * 4);
            va[i] = v;
            int gn = n0 + row;
            float4 wh = make_float4(0.f, 0.f, 0.f, 0.f);
            float4 wl = make_float4(0.f, 0.f, 0.f, 0.f);
            if (gn < N) {
                wh = *(const float4*)(Bph + (size_t)gn * K + k0 + qq * 4);
                wl = *(const float4*)(Bpl + (size_t)gn * K + k0 + qq * 4);
            }
            vbh[i] = wh; vbl[i] = wl;
        }
    };
    auto store_s = [&](int buf) {
#pragma unroll
        for (int i = 0; i < 2; i++) {
            int idx = tid + i * 256;
            int row = idx >> 2;
            int qq = idx & 3;
            *(float4*)&As[buf][row][qq * 4]  = va[i];
            *(float4*)&Bhs[buf][row][qq * 4] = vbh[i];
            *(float4*)&Bls[buf][row][qq * 4] = vbl[i];
        }
    };

    load_g(0);
    store_s(0);
    __syncthreads();

    int buf = 0;
    for (int t = 0; t < total; t++) {
        if (t + 1 < total) load_g(t + 1);

#pragma unroll
        for (int kk = 0; kk < 2; kk++) {
            const int cb = kk * 8;

            // ---- A fragments via ldmatrix, split to (hi, lo) in registers ----
            uint32_t ah[2][4], al[2][4];
#pragma unroll
            for (int mt = 0; mt < 2; mt++) {
                int rowa = wm0 + mt * 16 + (lane & 7) + ((sel & 1) << 3);
                int cola = cb + ((sel >> 1) << 2);
                uint32_t r0, r1, r2, r3;
                LDSM4(r0, r1, r2, r3, smem_u32(&As[buf][rowa][cola]));
                split_f32(__uint_as_float(r0), ah[mt][0], al[mt][0]);
                split_f32(__uint_as_float(r1), ah[mt][1], al[mt][1]);
                split_f32(__uint_as_float(r2), ah[mt][2], al[mt][2]);
                split_f32(__uint_as_float(r3), ah[mt][3], al[mt][3]);
            }

            // ---- B fragments (pre-split weights): 2 n8 tiles per ldmatrix.x4 ----
#pragma unroll
            for (int ngp = 0; ngp < 4; ngp++) {
                int rowb = wn0 + ngp * 16 + (lane & 7) + ((sel >> 1) << 3);
                int colb = cb + ((sel & 1) << 2);
                uint32_t h0, h1, h2, h3, l0, l1, l2, l3;
                LDSM4(h0, h1, h2, h3, smem_u32(&Bhs[buf][rowb][colb]));
                LDSM4(l0, l1, l2, l3, smem_u32(&Bls[buf][rowb][colb]));
                uint32_t bh0[2] = {h0, h1}, bh1[2] = {h2, h3};
                uint32_t bl0[2] = {l0, l1}, bl1[2] = {l2, l3};
#pragma unroll
                for (int mt = 0; mt < 2; mt++) {
                    MMA_TF32(c[mt][2 * ngp],     ah[mt], bh0);
                    MMA_TF32(c[mt][2 * ngp],     ah[mt], bl0);
                    MMA_TF32(c[mt][2 * ngp],     al[mt], bh0);
                    MMA_TF32(c[mt][2 * ngp],     al[mt], bl0);
                    MMA_TF32(c[mt][2 * ngp + 1], ah[mt], bh1);
                    MMA_TF32(c[mt][2 * ngp + 1], ah[mt], bl1);
                    MMA_TF32(c[mt][2 * ngp + 1], al[mt], bh1);
                    MMA_TF32(c[mt][2 * ngp + 1], al[mt], bl1);
                }
            }
        }

        if (t + 1 < total) store_s(buf ^ 1);
        __syncthreads();
        buf ^= 1;
    }

    // epilogue: + bias, optional relu, guarded fp32 store
#pragma unroll
    for (int mt = 0; mt < 2; mt++) {
#pragma unroll
        for (int ng = 0; ng < 8; ng++) {
            int col = n0 + wn0 + ng * 8 + q * 2;
            if (col >= N) continue;
            float b0 = p.bias[col], b1 = p.bias[col + 1];
#pragma unroll
            for (int half = 0; half < 2; half++) {
                int row = m0 + wm0 + mt * 16 + g + half * 8;
                if (row >= p.M) continue;
                float v0 = c[mt][ng][half * 2 + 0] + b0;
                float v1 = c[mt][ng][half * 2 + 1] + b1;
                if (RELU) { v0 = fmaxf(v0, 0.0f); v1 = fmaxf(v1, 0.0f); }
                *(float2*)(p.out + (size_t)row * opitch + col) = make_float2(v0, v1);
            }
        }
    }
}

template <bool RELU>
static inline void launch_gemm(GP p0, GP p1, int nz, int N, int K, int opitch) {
    cudaFuncSetAttribute(gemm_tf32x4_kernel<RELU>,
                         cudaFuncAttributeMaxDynamicSharedMemorySize, SMEM_BYTES);
    int mmax = p0.M;
    if (nz > 1 && p1.M > mmax) mmax = p1.M;
    dim3 grid((N + 127) / 128, (mmax + 127) / 128, nz);
    gemm_tf32x4_kernel<RELU><<<grid, 256, SMEM_BYTES>>>(p0, p1, N, K, opitch);
}

// ---------------- combined SpMM gather (both directions in one launch) ----------------
__global__ void spmm_both_kernel() {
    int r = (blockIdx.x * blockDim.x + threadIdx.x) >> 5;
    if (r >= NCLS + NLITS) return;
    int lane = threadIdx.x & 31;

    const int* lst; int n; const float* in; float* outp;
    if (r < NCLS) {
        lst = g_cls_idx + (size_t)r * CLS_STRIDE; n = g_cls_len[r];
        in = g_mlpL; outp = g_msgC + (size_t)r * E;
    } else {
        int rr = r - NCLS;
        lst = g_lit_idx + (size_t)rr * LIT_STRIDE; n = g_lit_len[rr];
        in = g_mlpC; outp = g_msgL + (size_t)rr * E;
    }

    float4 acc = make_float4(0.f, 0.f, 0.f, 0.f);
    int j = 0;
    for (; j + 4 <= n; j += 4) {
        int i0 = lst[j], i1 = lst[j + 1], i2 = lst[j + 2], i3 = lst[j + 3];
        float4 v0 = ((const float4*)(in + (size_t)i0 * E))[lane];
        float4 v1 = ((const float4*)(in + (size_t)i1 * E))[lane];
        float4 v2 = ((const float4*)(in + (size_t)i2 * E))[lane];
        float4 v3 = ((const float4*)(in + (size_t)i3 * E))[lane];
        acc.x += v0.x + v1.x + v2.x + v3.x;
        acc.y += v0.y + v1.y + v2.y + v3.y;
        acc.z += v0.z + v1.z + v2.z + v3.z;
        acc.w += v0.w + v1.w + v2.w + v3.w;
    }
    for (; j < n; j++) {
        float4 v = ((const float4*)(in + (size_t)lst[j] * E))[lane];
        acc.x += v.x; acc.y += v.y; acc.z += v.z; acc.w += v.w;
    }
    ((float4*)outp)[lane] = acc;
}

// ---------------- LSTM pointwise (both node types) ----------------
__device__ __forceinline__ float sigmoidf_(float x) { return 1.0f / (1.0f + expf(-x)); }

__global__ void lstm_pointwise_both() {
    int i = blockIdx.x * blockDim.x + threadIdx.x;
    const int totalC = NCLS * E;
    if (i >= totalC + NLITS * E) return;

    const float* gmat; float* cvec; float* hvec; int e;
    if (i < totalC) { gmat = g_gatesC; cvec = g_Cc; hvec = g_Ch; e = i; }
    else            { gmat = g_gatesL; cvec = g_Lc; hvec = g_Lh; e = i - totalC; }

    int row = e >> 7;
    int col = e & (E - 1);
    const float* gr = gmat + (size_t)row * NG;
    float ig = sigmoidf_(gr[col]);
    float fg = sigmoidf_(gr[E + col]);
    float gg = tanhf(gr[2 * E + col]);
    float og = sigmoidf_(gr[3 * E + col]);
    float c2 = fg * cvec[e] + ig * gg;
    cvec[e] = c2;
    hvec[e] = og * tanhf(c2);
}

// ---------------- vote + reduction ----------------
__global__ void vote_partial_kernel(const float* __restrict__ X2,
                                    const float* __restrict__ W3,
                                    const float* __restrict__ b3,
                                    float* __restrict__ partials) {
    int warp = (blockIdx.x * blockDim.x + threadIdx.x) >> 5;
    int lane = threadIdx.x & 31;
    float vote = 0.0f;
    if (warp < NLITS) {
        const float* x = X2 + (size_t)warp * H2P;
        float s = 0.0f;
        for (int jj = lane; jj < H2; jj += 32) s += x[jj] * W3[jj];
#pragma unroll
        for (int o = 16; o; o >>= 1) s += __shfl_down_sync(0xffffffffu, s, o);
        if (lane == 0) vote = sigmoidf_(s + b3[0]);
    }
    __shared__ float sm[8];
    if (lane == 0) sm[threadIdx.x >> 5] = vote;
    __syncthreads();
    if (threadIdx.x == 0) {
        float t = 0.0f;
        for (int w = 0; w < 8; w++) t += sm[w];
        partials[blockIdx.x] = t;
    }
}

__global__ void finalize_kernel(const float* __restrict__ partials, int n,
                                float* __restrict__ out) {
    __shared__ float sm[512];
    float s = 0.0f;
    for (int i = threadIdx.x; i < n; i += blockDim.x) s += partials[i];
    sm[threadIdx.x] = s;
    __syncthreads();
    for (int o = 256; o; o >>= 1) {
        if (threadIdx.x < o) sm[threadIdx.x] += sm[threadIdx.x + o];
        __syncthreads();
    }
    if (threadIdx.x == 0) {
        float avg = sm[0] / (float)NLITS;
        out[0] = logf(avg / (1.0f - avg));
    }
}

// ---------------- host ----------------
#define SYM(var, sym) cudaGetSymbolAddress((void**)&var, sym)

static inline void split_w(const float* in, float* hi, float* lo, int rows, int K, int KP) {
    int n = rows * KP;
    split_weight_kernel<<<(n + 255) / 256, 256>>>(in, hi, lo, rows, K, KP);
}

extern "C" void kernel_launch(void* const* d_in, const int* in_sizes, int n_in,
                              void* d_out, int out_size) {
    const float* M      = (const float*)d_in[0];
    const float* L_init = (const float*)d_in[1];
    const float* C_init = (const float*)d_in[2];
    const float* LC_W1 = (const float*)d_in[3];  const float* LC_b1 = (const float*)d_in[4];
    const float* LC_W2 = (const float*)d_in[5];  const float* LC_b2 = (const float*)d_in[6];
    const float* LC_W3 = (const float*)d_in[7];  const float* LC_b3 = (const float*)d_in[8];
    const float* CL_W1 = (const float*)d_in[9];  const float* CL_b1 = (const float*)d_in[10];
    const float* CL_W2 = (const float*)d_in[11]; const float* CL_b2 = (const float*)d_in[12];
    const float* CL_W3 = (const float*)d_in[13]; const float* CL_b3 = (const float*)d_in[14];
    const float* L_Wih = (const float*)d_in[15]; const float* L_Whh = (const float*)d_in[16];
    const float* L_b   = (const float*)d_in[17];
    const float* C_Wih = (const float*)d_in[18]; const float* C_Whh = (const float*)d_in[19];
    const float* C_b   = (const float*)d_in[20];
    const float* V_W1 = (const float*)d_in[21];  const float* V_b1 = (const float*)d_in[22];
    const float* V_W2 = (const float*)d_in[23];  const float* V_b2 = (const float*)d_in[24];
    const float* V_W3 = (const float*)d_in[25];  const float* V_b3 = (const float*)d_in[26];
    float* out = (float*)d_out;

    float *Lh, *Ch, *b1L, *b1C, *b2L, *b2C, *mlpL, *mlpC, *msgL, *msgC;
    float *gatesC, *gatesL, *partials;
    float *LC1h,*LC1l,*LC2h,*LC2l,*LC3h,*LC3l,*CL1h,*CL1l,*CL2h,*CL2l,*CL3h,*CL3l;
    float *CWih,*CWil,*CWhh,*CWhl,*LWih,*LWil,*LWhh,*LWhl,*VW1h,*VW1l,*VW2h,*VW2l;
    SYM(Lh, g_Lh); SYM(Ch, g_Ch);
    SYM(b1L, g_b1L); SYM(b1C, g_b1C); SYM(b2L, g_b2L); SYM(b2C, g_b2C);
    SYM(mlpL, g_mlpL); SYM(mlpC, g_mlpC); SYM(msgL, g_msgL); SYM(msgC, g_msgC);
    SYM(gatesC, g_gatesC); SYM(gatesL, g_gatesL); SYM(partials, g_partials);
    SYM(LC1h, g_LC1h); SYM(LC1l, g_LC1l); SYM(LC2h, g_LC2h); SYM(LC2l, g_LC2l);
    SYM(LC3h, g_LC3h); SYM(LC3l, g_LC3l);
    SYM(CL1h, g_CL1h); SYM(CL1l, g_CL1l); SYM(CL2h, g_CL2h); SYM(CL2l, g_CL2l);
    SYM(CL3h, g_CL3h); SYM(CL3l, g_CL3l);
    SYM(CWih, g_CWih); SYM(CWil, g_CWil); SYM(CWhh, g_CWhh); SYM(CWhl, g_CWhl);
    SYM(LWih, g_LWih); SYM(LWil, g_LWil); SYM(LWhh, g_LWhh); SYM(LWhl, g_LWhl);
    SYM(VW1h, g_VW1h); SYM(VW1l, g_VW1l); SYM(VW2h, g_VW2h); SYM(VW2l, g_VW2l);

    // adjacency + weight splits + state init
    build_lit_kernel<<<(NLITS + 7) / 8, 256>>>(M);
    build_cls_kernel<<<(NCLS + 7) / 8, 256>>>(M);
    split_w(LC_W1, LC1h, LC1l, H1, E,  E);
    split_w(LC_W2, LC2h, LC2l, H2, H1, H1);
    split_w(LC_W3, LC3h, LC3l, E,  H2, H2P);
    split_w(CL_W1, CL1h, CL1l, H1, E,  E);
    split_w(CL_W2, CL2h, CL2l, H2, H1, H1);
    split_w(CL_W3, CL3h, CL3l, E,  H2, H2P);
    split_w(C_Wih, CWih, CWil, NG, E,  E);
    split_w(C_Whh, CWhh, CWhl, NG, E,  E);
    split_w(L_Wih, LWih, LWil, NG, E,  E);
    split_w(L_Whh, LWhh, LWhl, NG, E,  E);
    split_w(V_W1,  VW1h, VW1l, H1, E,  E);
    split_w(V_W2,  VW2h, VW2l, H2, H1, H1);
    init_states_kernel<<<((NLITS + NCLS) * E + 255) / 256, 256>>>(L_init, C_init);

    GP dummy = {};

    for (int t = 0; t < TSTEPS; t++) {
        // MLP layer 1: lits use LC weights, clauses use CL weights
        GP a1 = {{Lh}, {LC1h}, {LC1l}, LC_b1, b1L, NLITS, 1};
        GP b1 = {{Ch}, {CL1h}, {CL1l}, CL_b1, b1C, NCLS, 1};
        launch_gemm<true>(a1, b1, 2, H1, E, H1);

        // MLP layer 2
        GP a2 = {{b1L}, {LC2h}, {LC2l}, LC_b2, b2L, NLITS, 1};
        GP b2 = {{b1C}, {CL2h}, {CL2l}, CL_b2, b2C, NCLS, 1};
        launch_gemm<true>(a2, b2, 2, H2, H1, H2P);

        // MLP layer 3 (no relu), K padded to 208 (pad cols of b2 are static zeros)
        GP a3 = {{b2L}, {LC3h}, {LC3l}, LC_b3, mlpL, NLITS, 1};
        GP b3 = {{b2C}, {CL3h}, {CL3l}, CL_b3, mlpC, NCLS, 1};
        launch_gemm<false>(a3, b3, 2, E, H2P, E);

        // sparse aggregation (both directions, one launch)
        spmm_both_kernel<<<(NCLS + NLITS + 7) / 8, 256>>>();

        // LSTM gates: msgs@Wih^T + h@Whh^T + b (pre-update h)
        GP ga = {{msgC, Ch}, {CWih, CWhh}, {CWil, CWhl}, C_b, gatesC, NCLS, 2};
        GP gb = {{msgL, Lh}, {LWih, LWhh}, {LWil, LWhl}, L_b, gatesL, NLITS, 2};
        launch_gemm<false>(ga, gb, 2, NG, E, NG);

        // pointwise state update
        lstm_pointwise_both<<<((NCLS + NLITS) * E + 255) / 256, 256>>>();
    }

    // final vote MLP + mean + logit
    GP v1 = {{Lh}, {VW1h}, {VW1l}, V_b1, b1L, NLITS, 1};
    launch_gemm<true>(v1, dummy, 1, H1, E, H1);
    GP v2 = {{b1L}, {VW2h}, {VW2l}, V_b2, b2L, NLITS, 1};
    launch_gemm<true>(v2, dummy, 1, H2, H1, H2P);
    vote_partial_kernel<<<VOTE_BLOCKS, 256>>>(b2L, V_W3, V_b3, partials);
    finalize_kernel<<<1, 512>>>(partials, VOTE_BLOCKS, out);
}

// round 8
// speedup vs baseline: 1.1346x; 1.1346x over previous
#include <cuda_runtime.h>
#include <math.h>
#include <stdint.h>

// ---------------- problem constants ----------------
#define NLITS 4000
#define NCLS  8000
#define E     128
#define H1    400
#define H2    200
#define H2P   208          // H2 padded to multiple of 16
#define NG    512          // 4*E LSTM gates
#define TSTEPS 30
#define LIT_STRIDE 512
#define CLS_STRIDE 256
#define VOTE_BLOCKS ((NLITS + 7) / 8)

// GEMM tiling
#define BK 16
#define SPB 80             // smem row stride bytes (16 floats + 4 pad)
#define TILEB (128 * SPB)  // one 128 x BK tile: 10240 B
#define STAGE_BYTES (3 * TILEB)     // A, Bh, Bl
#define STAGES 3
#define GEMM_SMEM (STAGES * STAGE_BYTES)   // 92160 B

// ---------------- device scratch (static, BSS zero-init, allocation-free) ----------------
__device__ float g_Lh[NLITS * E], g_Lc[NLITS * E];
__device__ float g_Ch[NCLS * E],  g_Cc[NCLS * E];
__device__ float g_b1L[NLITS * H1], g_b1C[NCLS * H1];
__device__ float g_b2L[NLITS * H2P], g_b2C[NCLS * H2P];   // pad cols [200,208) stay 0
__device__ float g_mlpL[NLITS * E],  g_mlpC[NCLS * E];
__device__ float g_msgL[NLITS * E],  g_msgC[NCLS * E];
__device__ float g_gatesC[NCLS * NG], g_gatesL[NLITS * NG];

// pre-split weights (tf32-valued fp32 hi/lo), K padded where needed
__device__ float g_LC1h[H1 * E],   g_LC1l[H1 * E];
__device__ float g_LC2h[H2 * H1],  g_LC2l[H2 * H1];
__device__ float g_LC3h[E * H2P],  g_LC3l[E * H2P];
__device__ float g_CL1h[H1 * E],   g_CL1l[H1 * E];
__device__ float g_CL2h[H2 * H1],  g_CL2l[H2 * H1];
__device__ float g_CL3h[E * H2P],  g_CL3l[E * H2P];
__device__ float g_CWih[NG * E],   g_CWil[NG * E];
__device__ float g_CWhh[NG * E],   g_CWhl[NG * E];
__device__ float g_LWih[NG * E],   g_LWil[NG * E];
__device__ float g_LWhh[NG * E],   g_LWhl[NG * E];
__device__ float g_VW1h[H1 * E],   g_VW1l[H1 * E];
__device__ float g_VW2h[H2 * H1],  g_VW2l[H2 * H1];

__device__ int   g_lit_idx[(size_t)NLITS * LIT_STRIDE];
__device__ int   g_lit_len[NLITS];
__device__ int   g_cls_idx[(size_t)NCLS * CLS_STRIDE];
__device__ int   g_cls_len[NCLS];
__device__ float g_partials[VOTE_BLOCKS];

// ---------------- helpers ----------------
__device__ __forceinline__ unsigned smem_u32(const void* p) {
    return (unsigned)__cvta_generic_to_shared(p);
}
__device__ __forceinline__ void tf32_split(float v, uint32_t& h, uint32_t& l) {
    asm("cvt.rna.tf32.f32 %0, %1;" : "=r"(h) : "f"(v));
    float r = v - __uint_as_float(h);
    asm("cvt.rna.tf32.f32 %0, %1;" : "=r"(l) : "f"(r));
}
__device__ __forceinline__ void cp16(uint32_t dst, const void* src, bool valid) {
    int sz = valid ? 16 : 0;
    asm volatile("cp.async.cg.shared.global [%0], [%1], 16, %2;"
                 :: "r"(dst), "l"(src), "r"(sz) : "memory");
}
#define CP_COMMIT() asm volatile("cp.async.commit_group;" ::: "memory")
#define CP_WAIT1()  asm volatile("cp.async.wait_group 1;" ::: "memory")

#define LDSM4(R0, R1, R2, R3, ADDR)                                          \
    asm volatile("ldmatrix.sync.aligned.m8n8.x4.shared.b16 {%0,%1,%2,%3}, [%4];" \
                 : "=r"(R0), "=r"(R1), "=r"(R2), "=r"(R3) : "r"(ADDR))

#define MMA_TF32(C, A, B)                                              \
    asm volatile(                                                      \
        "mma.sync.aligned.m16n8k8.row.col.f32.tf32.tf32.f32 "          \
        "{%0,%1,%2,%3}, {%4,%5,%6,%7}, {%8,%9}, {%0,%1,%2,%3};"        \
        : "+f"((C)[0]), "+f"((C)[1]), "+f"((C)[2]), "+f"((C)[3])       \
        : "r"((A)[0]), "r"((A)[1]), "r"((A)[2]), "r"((A)[3]),          \
          "r"((B)[0]), "r"((B)[1]))

// ---------------- adjacency builders ----------------
__global__ void build_lit_kernel(const float* __restrict__ M) {
    int l = blockIdx.x * (blockDim.x >> 5) + (threadIdx.x >> 5);
    int lane = threadIdx.x & 31;
    if (l >= NLITS) return;
    const float* row = M + (size_t)l * NCLS;
    int cnt = 0;
    for (int c0 = 0; c0 < NCLS; c0 += 32) {
        float v = row[c0 + lane];
        unsigned mask = __ballot_sync(0xffffffffu, v != 0.0f);
        if (v != 0.0f) {
            int pos = cnt + __popc(mask & ((1u << lane) - 1u));
            if (pos < LIT_STRIDE) g_lit_idx[(size_t)l * LIT_STRIDE + pos] = c0 + lane;
        }
        cnt += __popc(mask);
    }
    if (lane == 0) g_lit_len[l] = cnt < LIT_STRIDE ? cnt : LIT_STRIDE;
}

__global__ void build_cls_kernel(const float* __restrict__ M) {
    int c = blockIdx.x * (blockDim.x >> 5) + (threadIdx.x >> 5);
    int lane = threadIdx.x & 31;
    if (c >= NCLS) return;
    int cnt = 0;
    for (int l0 = 0; l0 < NLITS; l0 += 32) {
        float v = M[(size_t)(l0 + lane) * NCLS + c];
        unsigned mask = __ballot_sync(0xffffffffu, v != 0.0f);
        if (v != 0.0f) {
            int pos = cnt + __popc(mask & ((1u << lane) - 1u));
            if (pos < CLS_STRIDE) g_cls_idx[(size_t)c * CLS_STRIDE + pos] = l0 + lane;
        }
        cnt += __popc(mask);
    }
    if (lane == 0) g_cls_len[c] = cnt < CLS_STRIDE ? cnt : CLS_STRIDE;
}

// ---------------- weight splitter (tf32 hi/lo, optional K padding) ----------------
__global__ void split_weight_kernel(const float* __restrict__ in, float* __restrict__ hi,
                                    float* __restrict__ lo, int rows, int K, int KP) {
    int i = blockIdx.x * blockDim.x + threadIdx.x;
    if (i >= rows * KP) return;
    int r = i / KP, k = i - r * KP;
    float v = (k < K) ? in[(size_t)r * K + k] : 0.0f;
    uint32_t h, l;
    tf32_split(v, h, l);
    hi[i] = __uint_as_float(h);
    lo[i] = __uint_as_float(l);
}

// ---------------- state init ----------------
__global__ void init_states_kernel(const float* __restrict__ L_init,
                                   const float* __restrict__ C_init) {
    int i = blockIdx.x * blockDim.x + threadIdx.x;
    const int totL = NLITS * E;
    if (i < totL) {
        g_Lh[i] = L_init[i & (E - 1)]; g_Lc[i] = 0.0f;
    } else if (i < totL + NCLS * E) {
        int j = i - totL;
        g_Ch[j] = C_init[j & (E - 1)]; g_Cc[j] = 0.0f;
    }
}

// ---------------- tf32x3 mma GEMM with 3-stage cp.async pipeline ----------------
// C = act( sum_seg A[seg] @ W[seg]^T + bias ); A:[M,K] fp32 row-major (pitch=K),
// W pre-split Wh/Wl:[N,K] (tf32-valued fp32). fp32 out.
struct GP {
    const float* A[2];
    const float* Bh[2];
    const float* Bl[2];
    const float* bias;
    float* out;
    int M;
    int nseg;
};

template <bool RELU>
__global__ void __launch_bounds__(256) gemm_tf32x3_kernel(GP p0, GP p1, int N, int K, int opitch)
{
    const GP p = (blockIdx.z == 0) ? p0 : p1;
    const int m0 = blockIdx.y * 128;
    if (m0 >= p.M) return;
    const int n0 = blockIdx.x * 128;

    extern __shared__ char smem[];
    const uint32_t sb = smem_u32(smem);

    const int tid = threadIdx.x;
    const int lane = tid & 31;
    const int wid = tid >> 5;
    const int wm0 = (wid & 3) * 32;   // 4 warps over M
    const int wn0 = (wid >> 2) * 64;  // 2 warps over N
    const int g = lane >> 2;
    const int q = lane & 3;
    const int sel = lane >> 3;

    const int ntiles = K / BK;
    const int total = ntiles * p.nseg;

    float c[2][8][4];
#pragma unroll
    for (int a = 0; a < 2; a++)
#pragma unroll
        for (int b = 0; b < 8; b++)
#pragma unroll
            for (int d = 0; d < 4; d++) c[a][b][d] = 0.0f;

    // issue async loads for k-tile ti into stage buffer
    auto load_stage = [&](int ti, int stage) {
        const int seg = ti / ntiles;
        const int k0 = (ti - seg * ntiles) * BK;
        const float* Ap  = p.A[seg];
        const float* Bph = p.Bh[seg];
        const float* Bpl = p.Bl[seg];
        const uint32_t base = sb + stage * STAGE_BYTES;
#pragma unroll
        for (int i = 0; i < 2; i++) {
            int cid = tid + i * 256;           // 0..511
            int row = cid >> 2;                // 0..127
            int col = cid & 3;                 // 16B chunk within BK row
            uint32_t doff = row * SPB + col * 16;
            bool va = (m0 + row < p.M);
            int ra = va ? (m0 + row) : 0;
            cp16(base + doff, Ap + (size_t)ra * K + k0 + col * 4, va);
            bool vb = (n0 + row < N);
            int rb = vb ? (n0 + row) : 0;
            cp16(base + TILEB + doff,     Bph + (size_t)rb * K + k0 + col * 4, vb);
            cp16(base + 2 * TILEB + doff, Bpl + (size_t)rb * K + k0 + col * 4, vb);
        }
        CP_COMMIT();
    };

    // prologue: fill STAGES-1 buffers
    load_stage(0, 0);
    if (total > 1) load_stage(1, 1);
    else CP_COMMIT();   // keep group count uniform

    for (int t = 0; t < total; t++) {
        CP_WAIT1();           // stage t complete (<=1 group pending)
        __syncthreads();      // all threads' waits done -> tile visible

        if (t + 2 < total) load_stage(t + 2, (t + 2) % STAGES);

        const int st = (t % STAGES) * STAGE_BYTES;
        const uint32_t Ab  = sb + st;
        const uint32_t Bhb = sb + st + TILEB;
        const uint32_t Blb = sb + st + 2 * TILEB;

#pragma unroll
        for (int kk = 0; kk < 2; kk++) {
            const int cb = kk * 8;

            uint32_t ah[2][4], al[2][4];
#pragma unroll
            for (int mt = 0; mt < 2; mt++) {
                int rowa = wm0 + mt * 16 + (lane & 7) + ((sel & 1) << 3);
                int cola = cb + ((sel >> 1) << 2);
                uint32_t r0, r1, r2, r3;
                LDSM4(r0, r1, r2, r3, Ab + rowa * SPB + cola * 4);
                tf32_split(__uint_as_float(r0), ah[mt][0], al[mt][0]);
                tf32_split(__uint_as_float(r1), ah[mt][1], al[mt][1]);
                tf32_split(__uint_as_float(r2), ah[mt][2], al[mt][2]);
                tf32_split(__uint_as_float(r3), ah[mt][3], al[mt][3]);
            }

#pragma unroll
            for (int ngp = 0; ngp < 4; ngp++) {
                int rowb = wn0 + ngp * 16 + (lane & 7) + ((sel >> 1) << 3);
                int colb = cb + ((sel & 1) << 2);
                uint32_t h0, h1, h2, h3, l0, l1, l2, l3;
                LDSM4(h0, h1, h2, h3, Bhb + rowb * SPB + colb * 4);
                LDSM4(l0, l1, l2, l3, Blb + rowb * SPB + colb * 4);
                uint32_t bh0[2] = {h0, h1}, bh1[2] = {h2, h3};
                uint32_t bl0[2] = {l0, l1}, bl1[2] = {l2, l3};
#pragma unroll
                for (int mt = 0; mt < 2; mt++) {
                    MMA_TF32(c[mt][2 * ngp],     ah[mt], bh0);
                    MMA_TF32(c[mt][2 * ngp],     ah[mt], bl0);
                    MMA_TF32(c[mt][2 * ngp],     al[mt], bh0);
                    MMA_TF32(c[mt][2 * ngp + 1], ah[mt], bh1);
                    MMA_TF32(c[mt][2 * ngp + 1], ah[mt], bl1);
                    MMA_TF32(c[mt][2 * ngp + 1], al[mt], bh1);
                }
            }
        }
        __syncthreads();      // all reads of this stage done before it is refilled
    }

    // epilogue: + bias, optional relu, guarded fp32 store
#pragma unroll
    for (int mt = 0; mt < 2; mt++) {
#pragma unroll
        for (int ng = 0; ng < 8; ng++) {
            int col = n0 + wn0 + ng * 8 + q * 2;
            if (col >= N) continue;
            float b0 = p.bias[col], b1 = p.bias[col + 1];
#pragma unroll
            for (int half = 0; half < 2; half++) {
                int row = m0 + wm0 + mt * 16 + g + half * 8;
                if (row >= p.M) continue;
                float v0 = c[mt][ng][half * 2 + 0] + b0;
                float v1 = c[mt][ng][half * 2 + 1] + b1;
                if (RELU) { v0 = fmaxf(v0, 0.0f); v1 = fmaxf(v1, 0.0f); }
                *(float2*)(p.out + (size_t)row * opitch + col) = make_float2(v0, v1);
            }
        }
    }
}

template <bool RELU>
static inline void launch_gemm(GP p0, GP p1, int nz, int N, int K, int opitch) {
    cudaFuncSetAttribute(gemm_tf32x3_kernel<RELU>,
                         cudaFuncAttributeMaxDynamicSharedMemorySize, GEMM_SMEM);
    int mmax = p0.M;
    if (nz > 1 && p1.M > mmax) mmax = p1.M;
    dim3 grid((N + 127) / 128, (mmax + 127) / 128, nz);
    gemm_tf32x3_kernel<RELU><<<grid, 256, GEMM_SMEM>>>(p0, p1, N, K, opitch);
}

// ---------------- combined SpMM gather (both directions) ----------------
__global__ void spmm_both_kernel() {
    int r = (blockIdx.x * blockDim.x + threadIdx.x) >> 5;
    if (r >= NCLS + NLITS) return;
    int lane = threadIdx.x & 31;

    const int* lst; int n; const float* in; float* outp;
    if (r < NCLS) {
        lst = g_cls_idx + (size_t)r * CLS_STRIDE; n = g_cls_len[r];
        in = g_mlpL; outp = g_msgC + (size_t)r * E;
    } else {
        int rr = r - NCLS;
        lst = g_lit_idx + (size_t)rr * LIT_STRIDE; n = g_lit_len[rr];
        in = g_mlpC; outp = g_msgL + (size_t)rr * E;
    }

    float4 acc = make_float4(0.f, 0.f, 0.f, 0.f);
    int j = 0;
    for (; j + 4 <= n; j += 4) {
        int i0 = lst[j], i1 = lst[j + 1], i2 = lst[j + 2], i3 = lst[j + 3];
        float4 v0 = ((const float4*)(in + (size_t)i0 * E))[lane];
        float4 v1 = ((const float4*)(in + (size_t)i1 * E))[lane];
        float4 v2 = ((const float4*)(in + (size_t)i2 * E))[lane];
        float4 v3 = ((const float4*)(in + (size_t)i3 * E))[lane];
        acc.x += v0.x + v1.x + v2.x + v3.x;
        acc.y += v0.y + v1.y + v2.y + v3.y;
        acc.z += v0.z + v1.z + v2.z + v3.z;
        acc.w += v0.w + v1.w + v2.w + v3.w;
    }
    for (; j < n; j++) {
        float4 v = ((const float4*)(in + (size_t)lst[j] * E))[lane];
        acc.x += v.x; acc.y += v.y; acc.z += v.z; acc.w += v.w;
    }
    ((float4*)outp)[lane] = acc;
}

// ---------------- LSTM pointwise (both node types) ----------------
__device__ __forceinline__ float sigmoidf_(float x) { return 1.0f / (1.0f + expf(-x)); }

__global__ void lstm_pointwise_both() {
    int i = blockIdx.x * blockDim.x + threadIdx.x;
    const int totalC = NCLS * E;
    if (i >= totalC + NLITS * E) return;

    const float* gmat; float* cvec; float* hvec; int e;
    if (i < totalC) { gmat = g_gatesC; cvec = g_Cc; hvec = g_Ch; e = i; }
    else            { gmat = g_gatesL; cvec = g_Lc; hvec = g_Lh; e = i - totalC; }

    int row = e >> 7;
    int col = e & (E - 1);
    const float* gr = gmat + (size_t)row * NG;
    float ig = sigmoidf_(gr[col]);
    float fg = sigmoidf_(gr[E + col]);
    float gg = tanhf(gr[2 * E + col]);
    float og = sigmoidf_(gr[3 * E + col]);
    float c2 = fg * cvec[e] + ig * gg;
    cvec[e] = c2;
    hvec[e] = og * tanhf(c2);
}

// ---------------- vote + reduction ----------------
__global__ void vote_partial_kernel(const float* __restrict__ X2,
                                    const float* __restrict__ W3,
                                    const float* __restrict__ b3,
                                    float* __restrict__ partials) {
    int warp = (blockIdx.x * blockDim.x + threadIdx.x) >> 5;
    int lane = threadIdx.x & 31;
    float vote = 0.0f;
    if (warp < NLITS) {
        const float* x = X2 + (size_t)warp * H2P;
        float s = 0.0f;
        for (int jj = lane; jj < H2; jj += 32) s += x[jj] * W3[jj];
#pragma unroll
        for (int o = 16; o; o >>= 1) s += __shfl_down_sync(0xffffffffu, s, o);
        if (lane == 0) vote = sigmoidf_(s + b3[0]);
    }
    __shared__ float sm[8];
    if (lane == 0) sm[threadIdx.x >> 5] = vote;
    __syncthreads();
    if (threadIdx.x == 0) {
        float t = 0.0f;
        for (int w = 0; w < 8; w++) t += sm[w];
        partials[blockIdx.x] = t;
    }
}

__global__ void finalize_kernel(const float* __restrict__ partials, int n,
                                float* __restrict__ out) {
    __shared__ float sm[512];
    float s = 0.0f;
    for (int i = threadIdx.x; i < n; i += blockDim.x) s += partials[i];
    sm[threadIdx.x] = s;
    __syncthreads();
    for (int o = 256; o; o >>= 1) {
        if (threadIdx.x < o) sm[threadIdx.x] += sm[threadIdx.x + o];
        __syncthreads();
    }
    if (threadIdx.x == 0) {
        float avg = sm[0] / (float)NLITS;
        out[0] = logf(avg / (1.0f - avg));
    }
}

// ---------------- host ----------------
#define SYM(var, sym) cudaGetSymbolAddress((void**)&var, sym)

static inline void split_w(const float* in, float* hi, float* lo, int rows, int K, int KP) {
    int n = rows * KP;
    split_weight_kernel<<<(n + 255) / 256, 256>>>(in, hi, lo, rows, K, KP);
}

extern "C" void kernel_launch(void* const* d_in, const int* in_sizes, int n_in,
                              void* d_out, int out_size) {
    const float* M      = (const float*)d_in[0];
    const float* L_init = (const float*)d_in[1];
    const float* C_init = (const float*)d_in[2];
    const float* LC_W1 = (const float*)d_in[3];  const float* LC_b1 = (const float*)d_in[4];
    const float* LC_W2 = (const float*)d_in[5];  const float* LC_b2 = (const float*)d_in[6];
    const float* LC_W3 = (const float*)d_in[7];  const float* LC_b3 = (const float*)d_in[8];
    const float* CL_W1 = (const float*)d_in[9];  const float* CL_b1 = (const float*)d_in[10];
    const float* CL_W2 = (const float*)d_in[11]; const float* CL_b2 = (const float*)d_in[12];
    const float* CL_W3 = (const float*)d_in[13]; const float* CL_b3 = (const float*)d_in[14];
    const float* L_Wih = (const float*)d_in[15]; const float* L_Whh = (const float*)d_in[16];
    const float* L_b   = (const float*)d_in[17];
    const float* C_Wih = (const float*)d_in[18]; const float* C_Whh = (const float*)d_in[19];
    const float* C_b   = (const float*)d_in[20];
    const float* V_W1 = (const float*)d_in[21];  const float* V_b1 = (const float*)d_in[22];
    const float* V_W2 = (const float*)d_in[23];  const float* V_b2 = (const float*)d_in[24];
    const float* V_W3 = (const float*)d_in[25];  const float* V_b3 = (const float*)d_in[26];
    float* out = (float*)d_out;

    float *Lh, *Ch, *b1L, *b1C, *b2L, *b2C, *mlpL, *mlpC, *msgL, *msgC;
    float *gatesC, *gatesL, *partials;
    float *LC1h,*LC1l,*LC2h,*LC2l,*LC3h,*LC3l,*CL1h,*CL1l,*CL2h,*CL2l,*CL3h,*CL3l;
    float *CWih,*CWil,*CWhh,*CWhl,*LWih,*LWil,*LWhh,*LWhl,*VW1h,*VW1l,*VW2h,*VW2l;
    SYM(Lh, g_Lh); SYM(Ch, g_Ch);
    SYM(b1L, g_b1L); SYM(b1C, g_b1C); SYM(b2L, g_b2L); SYM(b2C, g_b2C);
    SYM(mlpL, g_mlpL); SYM(mlpC, g_mlpC); SYM(msgL, g_msgL); SYM(msgC, g_msgC);
    SYM(gatesC, g_gatesC); SYM(gatesL, g_gatesL); SYM(partials, g_partials);
    SYM(LC1h, g_LC1h); SYM(LC1l, g_LC1l); SYM(LC2h, g_LC2h); SYM(LC2l, g_LC2l);
    SYM(LC3h, g_LC3h); SYM(LC3l, g_LC3l);
    SYM(CL1h, g_CL1h); SYM(CL1l, g_CL1l); SYM(CL2h, g_CL2h); SYM(CL2l, g_CL2l);
    SYM(CL3h, g_CL3h); SYM(CL3l, g_CL3l);
    SYM(CWih, g_CWih); SYM(CWil, g_CWil); SYM(CWhh, g_CWhh); SYM(CWhl, g_CWhl);
    SYM(LWih, g_LWih); SYM(LWil, g_LWil); SYM(LWhh, g_LWhh); SYM(LWhl, g_LWhl);
    SYM(VW1h, g_VW1h); SYM(VW1l, g_VW1l); SYM(VW2h, g_VW2h); SYM(VW2l, g_VW2l);

    // adjacency + weight splits + state init
    build_lit_kernel<<<(NLITS + 7) / 8, 256>>>(M);
    build_cls_kernel<<<(NCLS + 7) / 8, 256>>>(M);
    split_w(LC_W1, LC1h, LC1l, H1, E,  E);
    split_w(LC_W2, LC2h, LC2l, H2, H1, H1);
    split_w(LC_W3, LC3h, LC3l, E,  H2, H2P);
    split_w(CL_W1, CL1h, CL1l, H1, E,  E);
    split_w(CL_W2, CL2h, CL2l, H2, H1, H1);
    split_w(CL_W3, CL3h, CL3l, E,  H2, H2P);
    split_w(C_Wih, CWih, CWil, NG, E,  E);
    split_w(C_Whh, CWhh, CWhl, NG, E,  E);
    split_w(L_Wih, LWih, LWil, NG, E,  E);
    split_w(L_Whh, LWhh, LWhl, NG, E,  E);
    split_w(V_W1,  VW1h, VW1l, H1, E,  E);
    split_w(V_W2,  VW2h, VW2l, H2, H1, H1);
    init_states_kernel<<<((NLITS + NCLS) * E + 255) / 256, 256>>>(L_init, C_init);

    GP dummy = {};

    for (int t = 0; t < TSTEPS; t++) {
        // MLP layer 1: lits use LC weights, clauses use CL weights
        GP a1 = {{Lh}, {LC1h}, {LC1l}, LC_b1, b1L, NLITS, 1};
        GP b1 = {{Ch}, {CL1h}, {CL1l}, CL_b1, b1C, NCLS, 1};
        launch_gemm<true>(a1, b1, 2, H1, E, H1);

        // MLP layer 2 (K=400, multiple of 16)
        GP a2 = {{b1L}, {LC2h}, {LC2l}, LC_b2, b2L, NLITS, 1};
        GP b2 = {{b1C}, {CL2h}, {CL2l}, CL_b2, b2C, NCLS, 1};
        launch_gemm<true>(a2, b2, 2, H2, H1, H2P);

        // MLP layer 3 (no relu; K padded to 208, pad cols of b2 are static zeros)
        GP a3 = {{b2L}, {LC3h}, {LC3l}, LC_b3, mlpL, NLITS, 1};
        GP b3 = {{b2C}, {CL3h}, {CL3l}, CL_b3, mlpC, NCLS, 1};
        launch_gemm<false>(a3, b3, 2, E, H2P, E);

        // sparse aggregation (both directions, one launch)
        spmm_both_kernel<<<(NCLS + NLITS + 7) / 8, 256>>>();

        // LSTM gates: msgs@Wih^T + h@Whh^T + b (pre-update h)
        GP ga = {{msgC, Ch}, {CWih, CWhh}, {CWil, CWhl}, C_b, gatesC, NCLS, 2};
        GP gb = {{msgL, Lh}, {LWih, LWhh}, {LWil, LWhl}, L_b, gatesL, NLITS, 2};
        launch_gemm<false>(ga, gb, 2, NG, E, NG);

        // pointwise state update
        lstm_pointwise_both<<<((NCLS + NLITS) * E + 255) / 256, 256>>>();
    }

    // final vote MLP + mean + logit
    GP v1 = {{Lh}, {VW1h}, {VW1l}, V_b1, b1L, NLITS, 1};
    launch_gemm<true>(v1, dummy, 1, H1, E, H1);
    GP v2 = {{b1L}, {VW2h}, {VW2l}, V_b2, b2L, NLITS, 1};
    launch_gemm<true>(v2, dummy, 1, H2, H1, H2P);
    vote_partial_kernel<<<VOTE_BLOCKS, 256>>>(b2L, V_W3, V_b3, partials);
    finalize_kernel<<<1, 512>>>(partials, VOTE_BLOCKS, out);
}

// round 9
// speedup vs baseline: 1.2433x; 1.0958x over previous
#include <cuda_runtime.h>
#include <math.h>
#include <stdint.h>

// ---------------- problem constants ----------------
#define NLITS 4000
#define NCLS  8000
#define E     128
#define H1    400
#define H2    200
#define H2P   208          // H2 padded to multiple of 16
#define NG    512          // 4*E LSTM gates
#define TSTEPS 30
#define LIT_STRIDE 512
#define CLS_STRIDE 256
#define VOTE_BLOCKS ((NLITS + 7) / 8)

// GEMM tiling
#define BK 16
#define SPB 80             // smem row stride bytes (16 floats + 4 pad)
#define TILEB (128 * SPB)  // one 128 x BK tile: 10240 B
#define STAGE_BYTES (3 * TILEB)     // A, Bh, Bl
#define STAGES 3
#define GEMM_SMEM (STAGES * STAGE_BYTES)   // 92160 B (2 blocks/SM: 184320 <= 228KB)

// ---------------- device scratch (static, BSS zero-init, allocation-free) ----------------
__device__ float g_Lh[NLITS * E], g_Lc[NLITS * E];
__device__ float g_Ch[NCLS * E],  g_Cc[NCLS * E];
__device__ float g_b1L[NLITS * H1], g_b1C[NCLS * H1];
__device__ float g_b2L[NLITS * H2P], g_b2C[NCLS * H2P];   // pad cols [200,208) stay 0
__device__ float g_mlpL[NLITS * E],  g_mlpC[NCLS * E];
__device__ float g_msgL[NLITS * E],  g_msgC[NCLS * E];
__device__ float g_gatesC[NCLS * NG], g_gatesL[NLITS * NG];

// pre-split weights (tf32-valued fp32 hi/lo), K padded where needed
__device__ float g_LC1h[H1 * E],   g_LC1l[H1 * E];
__device__ float g_LC2h[H2 * H1],  g_LC2l[H2 * H1];
__device__ float g_LC3h[E * H2P],  g_LC3l[E * H2P];
__device__ float g_CL1h[H1 * E],   g_CL1l[H1 * E];
__device__ float g_CL2h[H2 * H1],  g_CL2l[H2 * H1];
__device__ float g_CL3h[E * H2P],  g_CL3l[E * H2P];
__device__ float g_CWih[NG * E],   g_CWil[NG * E];
__device__ float g_CWhh[NG * E],   g_CWhl[NG * E];
__device__ float g_LWih[NG * E],   g_LWil[NG * E];
__device__ float g_LWhh[NG * E],   g_LWhl[NG * E];
__device__ float g_VW1h[H1 * E],   g_VW1l[H1 * E];
__device__ float g_VW2h[H2 * H1],  g_VW2l[H2 * H1];

__device__ int   g_lit_idx[(size_t)NLITS * LIT_STRIDE];
__device__ int   g_lit_len[NLITS];
__device__ int   g_cls_idx[(size_t)NCLS * CLS_STRIDE];
__device__ int   g_cls_len[NCLS];
__device__ float g_partials[VOTE_BLOCKS];

// ---------------- helpers ----------------
__device__ __forceinline__ unsigned smem_u32(const void* p) {
    return (unsigned)__cvta_generic_to_shared(p);
}
__device__ __forceinline__ void tf32_split(float v, uint32_t& h, uint32_t& l) {
    asm("cvt.rna.tf32.f32 %0, %1;" : "=r"(h) : "f"(v));
    float r = v - __uint_as_float(h);
    asm("cvt.rna.tf32.f32 %0, %1;" : "=r"(l) : "f"(r));
}
__device__ __forceinline__ void cp16(uint32_t dst, const void* src, bool valid) {
    int sz = valid ? 16 : 0;
    asm volatile("cp.async.cg.shared.global [%0], [%1], 16, %2;"
                 :: "r"(dst), "l"(src), "r"(sz) : "memory");
}
#define CP_COMMIT() asm volatile("cp.async.commit_group;" ::: "memory")
#define CP_WAIT1()  asm volatile("cp.async.wait_group 1;" ::: "memory")
#define CP_WAIT0()  asm volatile("cp.async.wait_group 0;" ::: "memory")

#define LDSM4(R0, R1, R2, R3, ADDR)                                          \
    asm volatile("ldmatrix.sync.aligned.m8n8.x4.shared.b16 {%0,%1,%2,%3}, [%4];" \
                 : "=r"(R0), "=r"(R1), "=r"(R2), "=r"(R3) : "r"(ADDR))

#define MMA_TF32(C, A, B)                                              \
    asm volatile(                                                      \
        "mma.sync.aligned.m16n8k8.row.col.f32.tf32.tf32.f32 "          \
        "{%0,%1,%2,%3}, {%4,%5,%6,%7}, {%8,%9}, {%0,%1,%2,%3};"        \
        : "+f"((C)[0]), "+f"((C)[1]), "+f"((C)[2]), "+f"((C)[3])       \
        : "r"((A)[0]), "r"((A)[1]), "r"((A)[2]), "r"((A)[3]),          \
          "r"((B)[0]), "r"((B)[1]))

// ---------------- merged adjacency builder (1 launch) ----------------
// blocks [0, 500): literals (8 warps -> 8 rows); blocks [500, 1500): clauses
#define LIT_BLOCKS ((NLITS + 7) / 8)
#define CLS_BLOCKS ((NCLS + 7) / 8)

__global__ void build_both_kernel(const float* __restrict__ M) {
    int lane = threadIdx.x & 31;
    int wslot = threadIdx.x >> 5;
    if (blockIdx.x < LIT_BLOCKS) {
        int l = blockIdx.x * 8 + wslot;
        if (l >= NLITS) return;
        const float* row = M + (size_t)l * NCLS;
        int cnt = 0;
        for (int c0 = 0; c0 < NCLS; c0 += 32) {
            float v = row[c0 + lane];
            unsigned mask = __ballot_sync(0xffffffffu, v != 0.0f);
            if (v != 0.0f) {
                int pos = cnt + __popc(mask & ((1u << lane) - 1u));
                if (pos < LIT_STRIDE) g_lit_idx[(size_t)l * LIT_STRIDE + pos] = c0 + lane;
            }
            cnt += __popc(mask);
        }
        if (lane == 0) g_lit_len[l] = cnt < LIT_STRIDE ? cnt : LIT_STRIDE;
    } else {
        int c = (blockIdx.x - LIT_BLOCKS) * 8 + wslot;
        if (c >= NCLS) return;
        int cnt = 0;
        for (int l0 = 0; l0 < NLITS; l0 += 32) {
            float v = M[(size_t)(l0 + lane) * NCLS + c];
            unsigned mask = __ballot_sync(0xffffffffu, v != 0.0f);
            if (v != 0.0f) {
                int pos = cnt + __popc(mask & ((1u << lane) - 1u));
                if (pos < CLS_STRIDE) g_cls_idx[(size_t)c * CLS_STRIDE + pos] = l0 + lane;
            }
            cnt += __popc(mask);
        }
        if (lane == 0) g_cls_len[c] = cnt < CLS_STRIDE ? cnt : CLS_STRIDE;
    }
}

// ---------------- consolidated weight splitter (1 launch, 12 weights) ----------------
struct WSplit { const float* in; float* hi; float* lo; int rows, K, KP; };
struct WSplitAll { WSplit w[12]; };

__global__ void split_all_kernel(WSplitAll all) {
    const WSplit w = all.w[blockIdx.y];
    int i = blockIdx.x * blockDim.x + threadIdx.x;
    if (i >= w.rows * w.KP) return;
    int r = i / w.KP, k = i - r * w.KP;
    float v = (k < w.K) ? w.in[(size_t)r * w.K + k] : 0.0f;
    uint32_t h, l;
    tf32_split(v, h, l);
    w.hi[i] = __uint_as_float(h);
    w.lo[i] = __uint_as_float(l);
}

// ---------------- state init ----------------
__global__ void init_states_kernel(const float* __restrict__ L_init,
                                   const float* __restrict__ C_init) {
    int i = blockIdx.x * blockDim.x + threadIdx.x;
    const int totL = NLITS * E;
    if (i < totL) {
        g_Lh[i] = L_init[i & (E - 1)]; g_Lc[i] = 0.0f;
    } else if (i < totL + NCLS * E) {
        int j = i - totL;
        g_Ch[j] = C_init[j & (E - 1)]; g_Cc[j] = 0.0f;
    }
}

// ---------------- tf32x3 mma GEMM, 3-stage cp.async pipeline, occ=2 ----------------
// C = act( sum_seg A[seg] @ W[seg]^T + bias ); A:[M,K] fp32 row-major (pitch=K),
// W pre-split Wh/Wl:[N,K] (tf32-valued fp32). fp32 out.
struct GP {
    const float* A[2];
    const float* Bh[2];
    const float* Bl[2];
    const float* bias;
    float* out;
    int M;
    int nseg;
};

template <bool RELU>
__global__ void __launch_bounds__(256, 2) gemm_tf32x3_kernel(GP p0, GP p1, int N, int K, int opitch)
{
    const GP p = (blockIdx.z == 0) ? p0 : p1;
    const int m0 = blockIdx.y * 128;
    if (m0 >= p.M) return;
    const int n0 = blockIdx.x * 128;

    extern __shared__ char smem[];
    const uint32_t sb = smem_u32(smem);

    const int tid = threadIdx.x;
    const int lane = tid & 31;
    const int wid = tid >> 5;
    const int wm0 = (wid & 3) * 32;   // 4 warps over M
    const int wn0 = (wid >> 2) * 64;  // 2 warps over N
    const int g = lane >> 2;
    const int q = lane & 3;
    const int sel = lane >> 3;

    const int ntiles = K / BK;
    const int total = ntiles * p.nseg;

    float c[2][8][4];
#pragma unroll
    for (int a = 0; a < 2; a++)
#pragma unroll
        for (int b = 0; b < 8; b++)
#pragma unroll
            for (int d = 0; d < 4; d++) c[a][b][d] = 0.0f;

    // issue async loads for k-tile ti into stage buffer
    auto load_stage = [&](int ti, int stage) {
        const int seg = ti / ntiles;
        const int k0 = (ti - seg * ntiles) * BK;
        const float* Ap  = p.A[seg];
        const float* Bph = p.Bh[seg];
        const float* Bpl = p.Bl[seg];
        const uint32_t base = sb + stage * STAGE_BYTES;
#pragma unroll
        for (int i = 0; i < 2; i++) {
            int cid = tid + i * 256;           // 0..511
            int row = cid >> 2;                // 0..127
            int col = cid & 3;                 // 16B chunk within BK row
            uint32_t doff = row * SPB + col * 16;
            bool va = (m0 + row < p.M);
            int ra = va ? (m0 + row) : 0;
            cp16(base + doff, Ap + (size_t)ra * K + k0 + col * 4, va);
            bool vb = (n0 + row < N);
            int rb = vb ? (n0 + row) : 0;
            cp16(base + TILEB + doff,     Bph + (size_t)rb * K + k0 + col * 4, vb);
            cp16(base + 2 * TILEB + doff, Bpl + (size_t)rb * K + k0 + col * 4, vb);
        }
        CP_COMMIT();
    };

    // prologue: fill up to 2 stages
    load_stage(0, 0);
    if (total > 1) load_stage(1, 1);
    else CP_COMMIT();   // keep group count uniform

    for (int t = 0; t < total; t++) {
        // stage t must be complete before reading. Groups complete in order;
        // the only group allowed pending is t+1 (if it exists).
        if (t + 1 < total) { CP_WAIT1(); } else { CP_WAIT0(); }
        __syncthreads();      // cross-thread visibility of stage t AND
                              // guarantees all warps finished reading stage t-1
                              // before anyone overwrites it below.

        if (t + 2 < total) load_stage(t + 2, (t + 2) % STAGES);

        const int st = (t % STAGES) * STAGE_BYTES;
        const uint32_t Ab  = sb + st;
        const uint32_t Bhb = sb + st + TILEB;
        const uint32_t Blb = sb + st + 2 * TILEB;

#pragma unroll
        for (int kk = 0; kk < 2; kk++) {
            const int cb = kk * 8;

            uint32_t ah[2][4], al[2][4];
#pragma unroll
            for (int mt = 0; mt < 2; mt++) {
                int rowa = wm0 + mt * 16 + (lane & 7) + ((sel & 1) << 3);
                int cola = cb + ((sel >> 1) << 2);
                uint32_t r0, r1, r2, r3;
                LDSM4(r0, r1, r2, r3, Ab + rowa * SPB + cola * 4);
                tf32_split(__uint_as_float(r0), ah[mt][0], al[mt][0]);
                tf32_split(__uint_as_float(r1), ah[mt][1], al[mt][1]);
                tf32_split(__uint_as_float(r2), ah[mt][2], al[mt][2]);
                tf32_split(__uint_as_float(r3), ah[mt][3], al[mt][3]);
            }

#pragma unroll
            for (int ngp = 0; ngp < 4; ngp++) {
                int rowb = wn0 + ngp * 16 + (lane & 7) + ((sel >> 1) << 3);
                int colb = cb + ((sel & 1) << 2);
                uint32_t h0, h1, h2, h3, l0, l1, l2, l3;
                LDSM4(h0, h1, h2, h3, Bhb + rowb * SPB + colb * 4);
                LDSM4(l0, l1, l2, l3, Blb + rowb * SPB + colb * 4);
                uint32_t bh0[2] = {h0, h1}, bh1[2] = {h2, h3};
                uint32_t bl0[2] = {l0, l1}, bl1[2] = {l2, l3};
#pragma unroll
                for (int mt = 0; mt < 2; mt++) {
                    MMA_TF32(c[mt][2 * ngp],     ah[mt], bh0);
                    MMA_TF32(c[mt][2 * ngp],     ah[mt], bl0);
                    MMA_TF32(c[mt][2 * ngp],     al[mt], bh0);
                    MMA_TF32(c[mt][2 * ngp + 1], ah[mt], bh1);
                    MMA_TF32(c[mt][2 * ngp + 1], ah[mt], bl1);
                    MMA_TF32(c[mt][2 * ngp + 1], al[mt], bh1);
                }
            }
        }
        // no trailing sync: next iteration's top sync orders reads vs refill
    }

    // epilogue: + bias, optional relu, guarded fp32 store
#pragma unroll
    for (int mt = 0; mt < 2; mt++) {
#pragma unroll
        for (int ng = 0; ng < 8; ng++) {
            int col = n0 + wn0 + ng * 8 + q * 2;
            if (col >= N) continue;
            float b0 = p.bias[col], b1 = p.bias[col + 1];
#pragma unroll
            for (int half = 0; half < 2; half++) {
                int row = m0 + wm0 + mt * 16 + g + half * 8;
                if (row >= p.M) continue;
                float v0 = c[mt][ng][half * 2 + 0] + b0;
                float v1 = c[mt][ng][half * 2 + 1] + b1;
                if (RELU) { v0 = fmaxf(v0, 0.0f); v1 = fmaxf(v1, 0.0f); }
                *(float2*)(p.out + (size_t)row * opitch + col) = make_float2(v0, v1);
            }
        }
    }
}

template <bool RELU>
static inline void launch_gemm(GP p0, GP p1, int nz, int N, int K, int opitch) {
    cudaFuncSetAttribute(gemm_tf32x3_kernel<RELU>,
                         cudaFuncAttributeMaxDynamicSharedMemorySize, GEMM_SMEM);
    int mmax = p0.M;
    if (nz > 1 && p1.M > mmax) mmax = p1.M;
    dim3 grid((N + 127) / 128, (mmax + 127) / 128, nz);
    gemm_tf32x3_kernel<RELU><<<grid, 256, GEMM_SMEM>>>(p0, p1, N, K, opitch);
}

// ---------------- combined SpMM gather (both directions) ----------------
__global__ void spmm_both_kernel() {
    int r = (blockIdx.x * blockDim.x + threadIdx.x) >> 5;
    if (r >= NCLS + NLITS) return;
    int lane = threadIdx.x & 31;

    const int* lst; int n; const float* in; float* outp;
    if (r < NCLS) {
        lst = g_cls_idx + (size_t)r * CLS_STRIDE; n = g_cls_len[r];
        in = g_mlpL; outp = g_msgC + (size_t)r * E;
    } else {
        int rr = r - NCLS;
        lst = g_lit_idx + (size_t)rr * LIT_STRIDE; n = g_lit_len[rr];
        in = g_mlpC; outp = g_msgL + (size_t)rr * E;
    }

    float4 acc = make_float4(0.f, 0.f, 0.f, 0.f);
    int j = 0;
    for (; j + 4 <= n; j += 4) {
        int i0 = lst[j], i1 = lst[j + 1], i2 = lst[j + 2], i3 = lst[j + 3];
        float4 v0 = ((const float4*)(in + (size_t)i0 * E))[lane];
        float4 v1 = ((const float4*)(in + (size_t)i1 * E))[lane];
        float4 v2 = ((const float4*)(in + (size_t)i2 * E))[lane];
        float4 v3 = ((const float4*)(in + (size_t)i3 * E))[lane];
        acc.x += v0.x + v1.x + v2.x + v3.x;
        acc.y += v0.y + v1.y + v2.y + v3.y;
        acc.z += v0.z + v1.z + v2.z + v3.z;
        acc.w += v0.w + v1.w + v2.w + v3.w;
    }
    for (; j < n; j++) {
        float4 v = ((const float4*)(in + (size_t)lst[j] * E))[lane];
        acc.x += v.x; acc.y += v.y; acc.z += v.z; acc.w += v.w;
    }
    ((float4*)outp)[lane] = acc;
}

// ---------------- LSTM pointwise (both node types) ----------------
__device__ __forceinline__ float sigmoidf_(float x) { return 1.0f / (1.0f + expf(-x)); }

__global__ void lstm_pointwise_both() {
    int i = blockIdx.x * blockDim.x + threadIdx.x;
    const int totalC = NCLS * E;
    if (i >= totalC + NLITS * E) return;

    const float* gmat; float* cvec; float* hvec; int e;
    if (i < totalC) { gmat = g_gatesC; cvec = g_Cc; hvec = g_Ch; e = i; }
    else            { gmat = g_gatesL; cvec = g_Lc; hvec = g_Lh; e = i - totalC; }

    int row = e >> 7;
    int col = e & (E - 1);
    const float* gr = gmat + (size_t)row * NG;
    float ig = sigmoidf_(gr[col]);
    float fg = sigmoidf_(gr[E + col]);
    float gg = tanhf(gr[2 * E + col]);
    float og = sigmoidf_(gr[3 * E + col]);
    float c2 = fg * cvec[e] + ig * gg;
    cvec[e] = c2;
    hvec[e] = og * tanhf(c2);
}

// ---------------- vote + reduction ----------------
__global__ void vote_partial_kernel(const float* __restrict__ X2,
                                    const float* __restrict__ W3,
                                    const float* __restrict__ b3,
                                    float* __restrict__ partials) {
    int warp = (blockIdx.x * blockDim.x + threadIdx.x) >> 5;
    int lane = threadIdx.x & 31;
    float vote = 0.0f;
    if (warp < NLITS) {
        const float* x = X2 + (size_t)warp * H2P;
        float s = 0.0f;
        for (int jj = lane; jj < H2; jj += 32) s += x[jj] * W3[jj];
#pragma unroll
        for (int o = 16; o; o >>= 1) s += __shfl_down_sync(0xffffffffu, s, o);
        if (lane == 0) vote = sigmoidf_(s + b3[0]);
    }
    __shared__ float sm[8];
    if (lane == 0) sm[threadIdx.x >> 5] = vote;
    __syncthreads();
    if (threadIdx.x == 0) {
        float t = 0.0f;
        for (int w = 0; w < 8; w++) t += sm[w];
        partials[blockIdx.x] = t;
    }
}

__global__ void finalize_kernel(const float* __restrict__ partials, int n,
                                float* __restrict__ out) {
    __shared__ float sm[512];
    float s = 0.0f;
    for (int i = threadIdx.x; i < n; i += blockDim.x) s += partials[i];
    sm[threadIdx.x] = s;
    __syncthreads();
    for (int o = 256; o; o >>= 1) {
        if (threadIdx.x < o) sm[threadIdx.x] += sm[threadIdx.x + o];
        __syncthreads();
    }
    if (threadIdx.x == 0) {
        float avg = sm[0] / (float)NLITS;
        out[0] = logf(avg / (1.0f - avg));
    }
}

// ---------------- host ----------------
#define SYM(var, sym) cudaGetSymbolAddress((void**)&var, sym)

extern "C" void kernel_launch(void* const* d_in, const int* in_sizes, int n_in,
                              void* d_out, int out_size) {
    const float* M      = (const float*)d_in[0];
    const float* L_init = (const float*)d_in[1];
    const float* C_init = (const float*)d_in[2];
    const float* LC_W1 = (const float*)d_in[3];  const float* LC_b1 = (const float*)d_in[4];
    const float* LC_W2 = (const float*)d_in[5];  const float* LC_b2 = (const float*)d_in[6];
    const float* LC_W3 = (const float*)d_in[7];  const float* LC_b3 = (const float*)d_in[8];
    const float* CL_W1 = (const float*)d_in[9];  const float* CL_b1 = (const float*)d_in[10];
    const float* CL_W2 = (const float*)d_in[11]; const float* CL_b2 = (const float*)d_in[12];
    const float* CL_W3 = (const float*)d_in[13]; const float* CL_b3 = (const float*)d_in[14];
    const float* L_Wih = (const float*)d_in[15]; const float* L_Whh = (const float*)d_in[16];
    const float* L_b   = (const float*)d_in[17];
    const float* C_Wih = (const float*)d_in[18]; const float* C_Whh = (const float*)d_in[19];
    const float* C_b   = (const float*)d_in[20];
    const float* V_W1 = (const float*)d_in[21];  const float* V_b1 = (const float*)d_in[22];
    const float* V_W2 = (const float*)d_in[23];  const float* V_b2 = (const float*)d_in[24];
    const float* V_W3 = (const float*)d_in[25];  const float* V_b3 = (const float*)d_in[26];
    float* out = (float*)d_out;

    float *Lh, *Ch, *b1L, *b1C, *b2L, *b2C, *mlpL, *mlpC, *msgL, *msgC;
    float *gatesC, *gatesL, *partials;
    float *LC1h,*LC1l,*LC2h,*LC2l,*LC3h,*LC3l,*CL1h,*CL1l,*CL2h,*CL2l,*CL3h,*CL3l;
    float *CWih,*CWil,*CWhh,*CWhl,*LWih,*LWil,*LWhh,*LWhl,*VW1h,*VW1l,*VW2h,*VW2l;
    SYM(Lh, g_Lh); SYM(Ch, g_Ch);
    SYM(b1L, g_b1L); SYM(b1C, g_b1C); SYM(b2L, g_b2L); SYM(b2C, g_b2C);
    SYM(mlpL, g_mlpL); SYM(mlpC, g_mlpC); SYM(msgL, g_msgL); SYM(msgC, g_msgC);
    SYM(gatesC, g_gatesC); SYM(gatesL, g_gatesL); SYM(partials, g_partials);
    SYM(LC1h, g_LC1h); SYM(LC1l, g_LC1l); SYM(LC2h, g_LC2h); SYM(LC2l, g_LC2l);
    SYM(LC3h, g_LC3h); SYM(LC3l, g_LC3l);
    SYM(CL1h, g_CL1h); SYM(CL1l, g_CL1l); SYM(CL2h, g_CL2h); SYM(CL2l, g_CL2l);
    SYM(CL3h, g_CL3h); SYM(CL3l, g_CL3l);
    SYM(CWih, g_CWih); SYM(CWil, g_CWil); SYM(CWhh, g_CWhh); SYM(CWhl, g_CWhl);
    SYM(LWih, g_LWih); SYM(LWil, g_LWil); SYM(LWhh, g_LWhh); SYM(LWhl, g_LWhl);
    SYM(VW1h, g_VW1h); SYM(VW1l, g_VW1l); SYM(VW2h, g_VW2h); SYM(VW2l, g_VW2l);

    // ---- setup: exactly 3 launches (so ncu -s 5 lands on a GEMM) ----
    build_both_kernel<<<LIT_BLOCKS + CLS_BLOCKS, 256>>>(M);

    WSplitAll ws = {{
        {LC_W1, LC1h, LC1l, H1, E,  E},
        {LC_W2, LC2h, LC2l, H2, H1, H1},
        {LC_W3, LC3h, LC3l, E,  H2, H2P},
        {CL_W1, CL1h, CL1l, H1, E,  E},
        {CL_W2, CL2h, CL2l, H2, H1, H1},
        {CL_W3, CL3h, CL3l, E,  H2, H2P},
        {C_Wih, CWih, CWil, NG, E,  E},
        {C_Whh, CWhh, CWhl, NG, E,  E},
        {L_Wih, LWih, LWil, NG, E,  E},
        {L_Whh, LWhh, LWhl, NG, E,  E},
        {V_W1,  VW1h, VW1l, H1, E,  E},
        {V_W2,  VW2h, VW2l, H2, H1, H1},
    }};
    dim3 sg((H2 * H1 + 255) / 256, 12);   // max weight = 80000 elems
    split_all_kernel<<<sg, 256>>>(ws);

    init_states_kernel<<<((NLITS + NCLS) * E + 255) / 256, 256>>>(L_init, C_init);

    GP dummy = {};

    for (int t = 0; t < TSTEPS; t++) {
        // MLP layer 1: lits use LC weights, clauses use CL weights
        GP a1 = {{Lh}, {LC1h}, {LC1l}, LC_b1, b1L, NLITS, 1};
        GP b1 = {{Ch}, {CL1h}, {CL1l}, CL_b1, b1C, NCLS, 1};
        launch_gemm<true>(a1, b1, 2, H1, E, H1);

        // MLP layer 2 (K=400, multiple of 16)
        GP a2 = {{b1L}, {LC2h}, {LC2l}, LC_b2, b2L, NLITS, 1};
        GP b2 = {{b1C}, {CL2h}, {CL2l}, CL_b2, b2C, NCLS, 1};
        launch_gemm<true>(a2, b2, 2, H2, H1, H2P);

        // MLP layer 3 (no relu; K padded to 208, pad cols of b2 are static zeros)
        GP a3 = {{b2L}, {LC3h}, {LC3l}, LC_b3, mlpL, NLITS, 1};
        GP b3 = {{b2C}, {CL3h}, {CL3l}, CL_b3, mlpC, NCLS, 1};
        launch_gemm<false>(a3, b3, 2, E, H2P, E);

        // sparse aggregation (both directions, one launch)
        spmm_both_kernel<<<(NCLS + NLITS + 7) / 8, 256>>>();

        // LSTM gates: msgs@Wih^T + h@Whh^T + b (pre-update h)
        GP ga = {{msgC, Ch}, {CWih, CWhh}, {CWil, CWhl}, C_b, gatesC, NCLS, 2};
        GP gb = {{msgL, Lh}, {LWih, LWhh}, {LWil, LWhl}, L_b, gatesL, NLITS, 2};
        launch_gemm<false>(ga, gb, 2, NG, E, NG);

        // pointwise state update
        lstm_pointwise_both<<<((NCLS + NLITS) * E + 255) / 256, 256>>>();
    }

    // final vote MLP + mean + logit
    GP v1 = {{Lh}, {VW1h}, {VW1l}, V_b1, b1L, NLITS, 1};
    launch_gemm<true>(v1, dummy, 1, H1, E, H1);
    GP v2 = {{b1L}, {VW2h}, {VW2l}, V_b2, b2L, NLITS, 1};
    launch_gemm<true>(v2, dummy, 1, H2, H1, H2P);
    vote_partial_kernel<<<VOTE_BLOCKS, 256>>>(b2L, V_W3, V_b3, partials);
    finalize_kernel<<<1, 512>>>(partials, VOTE_BLOCKS, out);
}

// round 10
// speedup vs baseline: 1.3270x; 1.0673x over previous
#include <cuda_runtime.h>
#include <math.h>
#include <stdint.h>

// ---------------- problem constants ----------------
#define NLITS 4000
#define NCLS  8000
#define E     128
#define H1    400
#define H2    200
#define H2P   208          // H2 padded to multiple of 16
#define NG    512          // 4*E LSTM gates
#define TSTEPS 30
#define LIT_STRIDE 512
#define CLS_STRIDE 256
#define VOTE_BLOCKS ((NLITS + 7) / 8)

// GEMM tiling: block tile 128(M) x 64(N), 8 warps (4 over M x 2 over N), warp tile 32x32
#define BK 16
#define SPB 80                  // smem row stride bytes (16 floats + 4 pad)
#define TILEB_A (128 * SPB)     // 10240 B
#define TILEB_B (64 * SPB)      // 5120 B
#define STAGE_BYTES (TILEB_A + 2 * TILEB_B)   // 20480 B (A, Bh, Bl)
#define STAGES 3
#define GEMM_SMEM (STAGES * STAGE_BYTES)      // 61440 B; 3 blocks/SM = 184320 <= 228KB

// ---------------- device scratch (static, BSS zero-init, allocation-free) ----------------
__device__ float g_Lh[NLITS * E], g_Lc[NLITS * E];
__device__ float g_Ch[NCLS * E],  g_Cc[NCLS * E];
__device__ float g_b1L[NLITS * H1], g_b1C[NCLS * H1];
__device__ float g_b2L[NLITS * H2P], g_b2C[NCLS * H2P];   // pad cols [200,208) stay 0
__device__ float g_mlpL[NLITS * E],  g_mlpC[NCLS * E];
__device__ float g_msgL[NLITS * E],  g_msgC[NCLS * E];
__device__ float g_gatesC[NCLS * NG], g_gatesL[NLITS * NG];

// pre-split weights (tf32-valued fp32 hi/lo), K padded where needed
__device__ float g_LC1h[H1 * E],   g_LC1l[H1 * E];
__device__ float g_LC2h[H2 * H1],  g_LC2l[H2 * H1];
__device__ float g_LC3h[E * H2P],  g_LC3l[E * H2P];
__device__ float g_CL1h[H1 * E],   g_CL1l[H1 * E];
__device__ float g_CL2h[H2 * H1],  g_CL2l[H2 * H1];
__device__ float g_CL3h[E * H2P],  g_CL3l[E * H2P];
__device__ float g_CWih[NG * E],   g_CWil[NG * E];
__device__ float g_CWhh[NG * E],   g_CWhl[NG * E];
__device__ float g_LWih[NG * E],   g_LWil[NG * E];
__device__ float g_LWhh[NG * E],   g_LWhl[NG * E];
__device__ float g_VW1h[H1 * E],   g_VW1l[H1 * E];
__device__ float g_VW2h[H2 * H1],  g_VW2l[H2 * H1];

__device__ int   g_lit_idx[(size_t)NLITS * LIT_STRIDE];
__device__ int   g_lit_len[NLITS];
__device__ int   g_cls_idx[(size_t)NCLS * CLS_STRIDE];
__device__ int   g_cls_len[NCLS];
__device__ float g_partials[VOTE_BLOCKS];

// ---------------- helpers ----------------
__device__ __forceinline__ unsigned smem_u32(const void* p) {
    return (unsigned)__cvta_generic_to_shared(p);
}
__device__ __forceinline__ void tf32_split(float v, uint32_t& h, uint32_t& l) {
    asm("cvt.rna.tf32.f32 %0, %1;" : "=r"(h) : "f"(v));
    float r = v - __uint_as_float(h);
    asm("cvt.rna.tf32.f32 %0, %1;" : "=r"(l) : "f"(r));
}
__device__ __forceinline__ void cp16(uint32_t dst, const void* src, bool valid) {
    int sz = valid ? 16 : 0;
    asm volatile("cp.async.cg.shared.global [%0], [%1], 16, %2;"
                 :: "r"(dst), "l"(src), "r"(sz) : "memory");
}
#define CP_COMMIT() asm volatile("cp.async.commit_group;" ::: "memory")
#define CP_WAIT1()  asm volatile("cp.async.wait_group 1;" ::: "memory")
#define CP_WAIT0()  asm volatile("cp.async.wait_group 0;" ::: "memory")

#define LDSM4(R0, R1, R2, R3, ADDR)                                          \
    asm volatile("ldmatrix.sync.aligned.m8n8.x4.shared.b16 {%0,%1,%2,%3}, [%4];" \
                 : "=r"(R0), "=r"(R1), "=r"(R2), "=r"(R3) : "r"(ADDR))

#define MMA_TF32(C, A, B)                                              \
    asm volatile(                                                      \
        "mma.sync.aligned.m16n8k8.row.col.f32.tf32.tf32.f32 "          \
        "{%0,%1,%2,%3}, {%4,%5,%6,%7}, {%8,%9}, {%0,%1,%2,%3};"        \
        : "+f"((C)[0]), "+f"((C)[1]), "+f"((C)[2]), "+f"((C)[3])       \
        : "r"((A)[0]), "r"((A)[1]), "r"((A)[2]), "r"((A)[3]),          \
          "r"((B)[0]), "r"((B)[1]))

// ---------------- merged adjacency builder (1 launch) ----------------
#define LIT_BLOCKS ((NLITS + 7) / 8)
#define CLS_BLOCKS ((NCLS + 7) / 8)

__global__ void build_both_kernel(const float* __restrict__ M) {
    int lane = threadIdx.x & 31;
    int wslot = threadIdx.x >> 5;
    if (blockIdx.x < LIT_BLOCKS) {
        int l = blockIdx.x * 8 + wslot;
        if (l >= NLITS) return;
        const float* row = M + (size_t)l * NCLS;
        int cnt = 0;
        for (int c0 = 0; c0 < NCLS; c0 += 32) {
            float v = row[c0 + lane];
            unsigned mask = __ballot_sync(0xffffffffu, v != 0.0f);
            if (v != 0.0f) {
                int pos = cnt + __popc(mask & ((1u << lane) - 1u));
                if (pos < LIT_STRIDE) g_lit_idx[(size_t)l * LIT_STRIDE + pos] = c0 + lane;
            }
            cnt += __popc(mask);
        }
        if (lane == 0) g_lit_len[l] = cnt < LIT_STRIDE ? cnt : LIT_STRIDE;
    } else {
        int c = (blockIdx.x - LIT_BLOCKS) * 8 + wslot;
        if (c >= NCLS) return;
        int cnt = 0;
        for (int l0 = 0; l0 < NLITS; l0 += 32) {
            float v = M[(size_t)(l0 + lane) * NCLS + c];
            unsigned mask = __ballot_sync(0xffffffffu, v != 0.0f);
            if (v != 0.0f) {
                int pos = cnt + __popc(mask & ((1u << lane) - 1u));
                if (pos < CLS_STRIDE) g_cls_idx[(size_t)c * CLS_STRIDE + pos] = l0 + lane;
            }
            cnt += __popc(mask);
        }
        if (lane == 0) g_cls_len[c] = cnt < CLS_STRIDE ? cnt : CLS_STRIDE;
    }
}

// ---------------- consolidated weight splitter (1 launch, 12 weights) ----------------
struct WSplit { const float* in; float* hi; float* lo; int rows, K, KP; };
struct WSplitAll { WSplit w[12]; };

__global__ void split_all_kernel(WSplitAll all) {
    const WSplit w = all.w[blockIdx.y];
    int i = blockIdx.x * blockDim.x + threadIdx.x;
    if (i >= w.rows * w.KP) return;
    int r = i / w.KP, k = i - r * w.KP;
    float v = (k < w.K) ? w.in[(size_t)r * w.K + k] : 0.0f;
    uint32_t h, l;
    tf32_split(v, h, l);
    w.hi[i] = __uint_as_float(h);
    w.lo[i] = __uint_as_float(l);
}

// ---------------- state init ----------------
__global__ void init_states_kernel(const float* __restrict__ L_init,
                                   const float* __restrict__ C_init) {
    int i = blockIdx.x * blockDim.x + threadIdx.x;
    const int totL = NLITS * E;
    if (i < totL) {
        g_Lh[i] = L_init[i & (E - 1)]; g_Lc[i] = 0.0f;
    } else if (i < totL + NCLS * E) {
        int j = i - totL;
        g_Ch[j] = C_init[j & (E - 1)]; g_Cc[j] = 0.0f;
    }
}

// ---------------- tf32x3 mma GEMM, 3-stage cp.async pipeline, 128x64 tile ----------------
struct GP {
    const float* A[2];
    const float* Bh[2];
    const float* Bl[2];
    const float* bias;
    float* out;
    int M;
    int nseg;
};

template <bool RELU>
__global__ void __launch_bounds__(256, 3) gemm_tf32x3_kernel(GP p0, GP p1, int N, int K, int opitch)
{
    const GP p = (blockIdx.z == 0) ? p0 : p1;
    const int m0 = blockIdx.y * 128;
    if (m0 >= p.M) return;
    const int n0 = blockIdx.x * 64;

    extern __shared__ char smem[];
    const uint32_t sb = smem_u32(smem);

    const int tid = threadIdx.x;
    const int lane = tid & 31;
    const int wid = tid >> 5;
    const int wm0 = (wid & 3) * 32;   // 4 warps over M
    const int wn0 = (wid >> 2) * 32;  // 2 warps over N
    const int g = lane >> 2;
    const int q = lane & 3;
    const int sel = lane >> 3;

    const int ntiles = K / BK;
    const int total = ntiles * p.nseg;

    float c[2][4][4];                 // 32 accumulators (warp tile 32x32)
#pragma unroll
    for (int a = 0; a < 2; a++)
#pragma unroll
        for (int b = 0; b < 4; b++)
#pragma unroll
            for (int d = 0; d < 4; d++) c[a][b][d] = 0.0f;

    // issue async loads for k-tile ti into stage buffer (4 cp16 per thread)
    auto load_stage = [&](int ti, int stage) {
        const int seg = ti / ntiles;
        const int k0 = (ti - seg * ntiles) * BK;
        const float* Ap  = p.A[seg];
        const float* Bph = p.Bh[seg];
        const float* Bpl = p.Bl[seg];
        const uint32_t base = sb + stage * STAGE_BYTES;
        // A: 128 rows x 4 chunks = 512 cp ops
#pragma unroll
        for (int i = 0; i < 2; i++) {
            int cid = tid + i * 256;
            int row = cid >> 2;
            int col = cid & 3;
            bool va = (m0 + row < p.M);
            int ra = va ? (m0 + row) : 0;
            cp16(base + row * SPB + col * 16, Ap + (size_t)ra * K + k0 + col * 4, va);
        }
        // Bh/Bl: 64 rows x 4 chunks = 256 cp ops each
        {
            int row = tid >> 2;
            int col = tid & 3;
            bool vb = (n0 + row < N);
            int rb = vb ? (n0 + row) : 0;
            uint32_t doff = row * SPB + col * 16;
            cp16(base + TILEB_A + doff,           Bph + (size_t)rb * K + k0 + col * 4, vb);
            cp16(base + TILEB_A + TILEB_B + doff, Bpl + (size_t)rb * K + k0 + col * 4, vb);
        }
        CP_COMMIT();
    };

    // prologue: fill up to 2 stages
    load_stage(0, 0);
    if (total > 1) load_stage(1, 1);
    else CP_COMMIT();   // keep group count uniform

    for (int t = 0; t < total; t++) {
        if (t + 1 < total) { CP_WAIT1(); } else { CP_WAIT0(); }
        __syncthreads();

        if (t + 2 < total) load_stage(t + 2, (t + 2) % STAGES);

        const int st = (t % STAGES) * STAGE_BYTES;
        const uint32_t Ab  = sb + st;
        const uint32_t Bhb = sb + st + TILEB_A;
        const uint32_t Blb = sb + st + TILEB_A + TILEB_B;

#pragma unroll
        for (int kk = 0; kk < 2; kk++) {
            const int cb = kk * 8;

            uint32_t ah[2][4], al[2][4];
#pragma unroll
            for (int mt = 0; mt < 2; mt++) {
                int rowa = wm0 + mt * 16 + (lane & 7) + ((sel & 1) << 3);
                int cola = cb + ((sel >> 1) << 2);
                uint32_t r0, r1, r2, r3;
                LDSM4(r0, r1, r2, r3, Ab + rowa * SPB + cola * 4);
                tf32_split(__uint_as_float(r0), ah[mt][0], al[mt][0]);
                tf32_split(__uint_as_float(r1), ah[mt][1], al[mt][1]);
                tf32_split(__uint_as_float(r2), ah[mt][2], al[mt][2]);
                tf32_split(__uint_as_float(r3), ah[mt][3], al[mt][3]);
            }

#pragma unroll
            for (int ngp = 0; ngp < 2; ngp++) {
                int rowb = wn0 + ngp * 16 + (lane & 7) + ((sel >> 1) << 3);
                int colb = cb + ((sel & 1) << 2);
                uint32_t h0, h1, h2, h3, l0, l1, l2, l3;
                LDSM4(h0, h1, h2, h3, Bhb + rowb * SPB + colb * 4);
                LDSM4(l0, l1, l2, l3, Blb + rowb * SPB + colb * 4);
                uint32_t bh0[2] = {h0, h1}, bh1[2] = {h2, h3};
                uint32_t bl0[2] = {l0, l1}, bl1[2] = {l2, l3};
#pragma unroll
                for (int mt = 0; mt < 2; mt++) {
                    MMA_TF32(c[mt][2 * ngp],     ah[mt], bh0);
                    MMA_TF32(c[mt][2 * ngp],     ah[mt], bl0);
                    MMA_TF32(c[mt][2 * ngp],     al[mt], bh0);
                    MMA_TF32(c[mt][2 * ngp + 1], ah[mt], bh1);
                    MMA_TF32(c[mt][2 * ngp + 1], ah[mt], bl1);
                    MMA_TF32(c[mt][2 * ngp + 1], al[mt], bh1);
                }
            }
        }
    }

    // epilogue: + bias, optional relu, guarded fp32 store
#pragma unroll
    for (int mt = 0; mt < 2; mt++) {
#pragma unroll
        for (int ng = 0; ng < 4; ng++) {
            int col = n0 + wn0 + ng * 8 + q * 2;
            if (col >= N) continue;
            float b0 = p.bias[col], b1 = p.bias[col + 1];
#pragma unroll
            for (int half = 0; half < 2; half++) {
                int row = m0 + wm0 + mt * 16 + g + half * 8;
                if (row >= p.M) continue;
                float v0 = c[mt][ng][half * 2 + 0] + b0;
                float v1 = c[mt][ng][half * 2 + 1] + b1;
                if (RELU) { v0 = fmaxf(v0, 0.0f); v1 = fmaxf(v1, 0.0f); }
                *(float2*)(p.out + (size_t)row * opitch + col) = make_float2(v0, v1);
            }
        }
    }
}

template <bool RELU>
static inline void launch_gemm(GP p0, GP p1, int nz, int N, int K, int opitch) {
    cudaFuncSetAttribute(gemm_tf32x3_kernel<RELU>,
                         cudaFuncAttributeMaxDynamicSharedMemorySize, GEMM_SMEM);
    int mmax = p0.M;
    if (nz > 1 && p1.M > mmax) mmax = p1.M;
    dim3 grid((N + 63) / 64, (mmax + 127) / 128, nz);
    gemm_tf32x3_kernel<RELU><<<grid, 256, GEMM_SMEM>>>(p0, p1, N, K, opitch);
}

// ---------------- combined SpMM gather (both directions) ----------------
__global__ void spmm_both_kernel() {
    int r = (blockIdx.x * blockDim.x + threadIdx.x) >> 5;
    if (r >= NCLS + NLITS) return;
    int lane = threadIdx.x & 31;

    const int* lst; int n; const float* in; float* outp;
    if (r < NCLS) {
        lst = g_cls_idx + (size_t)r * CLS_STRIDE; n = g_cls_len[r];
        in = g_mlpL; outp = g_msgC + (size_t)r * E;
    } else {
        int rr = r - NCLS;
        lst = g_lit_idx + (size_t)rr * LIT_STRIDE; n = g_lit_len[rr];
        in = g_mlpC; outp = g_msgL + (size_t)rr * E;
    }

    float4 acc = make_float4(0.f, 0.f, 0.f, 0.f);
    int j = 0;
    for (; j + 4 <= n; j += 4) {
        int i0 = lst[j], i1 = lst[j + 1], i2 = lst[j + 2], i3 = lst[j + 3];
        float4 v0 = ((const float4*)(in + (size_t)i0 * E))[lane];
        float4 v1 = ((const float4*)(in + (size_t)i1 * E))[lane];
        float4 v2 = ((const float4*)(in + (size_t)i2 * E))[lane];
        float4 v3 = ((const float4*)(in + (size_t)i3 * E))[lane];
        acc.x += v0.x + v1.x + v2.x + v3.x;
        acc.y += v0.y + v1.y + v2.y + v3.y;
        acc.z += v0.z + v1.z + v2.z + v3.z;
        acc.w += v0.w + v1.w + v2.w + v3.w;
    }
    for (; j < n; j++) {
        float4 v = ((const float4*)(in + (size_t)lst[j] * E))[lane];
        acc.x += v.x; acc.y += v.y; acc.z += v.z; acc.w += v.w;
    }
    ((float4*)outp)[lane] = acc;
}

// ---------------- LSTM pointwise (both node types) ----------------
__device__ __forceinline__ float sigmoidf_(float x) { return 1.0f / (1.0f + expf(-x)); }

__global__ void lstm_pointwise_both() {
    int i = blockIdx.x * blockDim.x + threadIdx.x;
    const int totalC = NCLS * E;
    if (i >= totalC + NLITS * E) return;

    const float* gmat; float* cvec; float* hvec; int e;
    if (i < totalC) { gmat = g_gatesC; cvec = g_Cc; hvec = g_Ch; e = i; }
    else            { gmat = g_gatesL; cvec = g_Lc; hvec = g_Lh; e = i - totalC; }

    int row = e >> 7;
    int col = e & (E - 1);
    const float* gr = gmat + (size_t)row * NG;
    float ig = sigmoidf_(gr[col]);
    float fg = sigmoidf_(gr[E + col]);
    float gg = tanhf(gr[2 * E + col]);
    float og = sigmoidf_(gr[3 * E + col]);
    float c2 = fg * cvec[e] + ig * gg;
    cvec[e] = c2;
    hvec[e] = og * tanhf(c2);
}

// ---------------- vote + reduction ----------------
__global__ void vote_partial_kernel(const float* __restrict__ X2,
                                    const float* __restrict__ W3,
                                    const float* __restrict__ b3,
                                    float* __restrict__ partials) {
    int warp = (blockIdx.x * blockDim.x + threadIdx.x) >> 5;
    int lane = threadIdx.x & 31;
    float vote = 0.0f;
    if (warp < NLITS) {
        const float* x = X2 + (size_t)warp * H2P;
        float s = 0.0f;
        for (int jj = lane; jj < H2; jj += 32) s += x[jj] * W3[jj];
#pragma unroll
        for (int o = 16; o; o >>= 1) s += __shfl_down_sync(0xffffffffu, s, o);
        if (lane == 0) vote = sigmoidf_(s + b3[0]);
    }
    __shared__ float sm[8];
    if (lane == 0) sm[threadIdx.x >> 5] = vote;
    __syncthreads();
    if (threadIdx.x == 0) {
        float t = 0.0f;
        for (int w = 0; w < 8; w++) t += sm[w];
        partials[blockIdx.x] = t;
    }
}

__global__ void finalize_kernel(const float* __restrict__ partials, int n,
                                float* __restrict__ out) {
    __shared__ float sm[512];
    float s = 0.0f;
    for (int i = threadIdx.x; i < n; i += blockDim.x) s += partials[i];
    sm[threadIdx.x] = s;
    __syncthreads();
    for (int o = 256; o; o >>= 1) {
        if (threadIdx.x < o) sm[threadIdx.x] += sm[threadIdx.x + o];
        __syncthreads();
    }
    if (threadIdx.x == 0) {
        float avg = sm[0] / (float)NLITS;
        out[0] = logf(avg / (1.0f - avg));
    }
}

// ---------------- host ----------------
#define SYM(var, sym) cudaGetSymbolAddress((void**)&var, sym)

extern "C" void kernel_launch(void* const* d_in, const int* in_sizes, int n_in,
                              void* d_out, int out_size) {
    const float* M      = (const float*)d_in[0];
    const float* L_init = (const float*)d_in[1];
    const float* C_init = (const float*)d_in[2];
    const float* LC_W1 = (const float*)d_in[3];  const float* LC_b1 = (const float*)d_in[4];
    const float* LC_W2 = (const float*)d_in[5];  const float* LC_b2 = (const float*)d_in[6];
    const float* LC_W3 = (const float*)d_in[7];  const float* LC_b3 = (const float*)d_in[8];
    const float* CL_W1 = (const float*)d_in[9];  const float* CL_b1 = (const float*)d_in[10];
    const float* CL_W2 = (const float*)d_in[11]; const float* CL_b2 = (const float*)d_in[12];
    const float* CL_W3 = (const float*)d_in[13]; const float* CL_b3 = (const float*)d_in[14];
    const float* L_Wih = (const float*)d_in[15]; const float* L_Whh = (const float*)d_in[16];
    const float* L_b   = (const float*)d_in[17];
    const float* C_Wih = (const float*)d_in[18]; const float* C_Whh = (const float*)d_in[19];
    const float* C_b   = (const float*)d_in[20];
    const float* V_W1 = (const float*)d_in[21];  const float* V_b1 = (const float*)d_in[22];
    const float* V_W2 = (const float*)d_in[23];  const float* V_b2 = (const float*)d_in[24];
    const float* V_W3 = (const float*)d_in[25];  const float* V_b3 = (const float*)d_in[26];
    float* out = (float*)d_out;

    float *Lh, *Ch, *b1L, *b1C, *b2L, *b2C, *mlpL, *mlpC, *msgL, *msgC;
    float *gatesC, *gatesL, *partials;
    float *LC1h,*LC1l,*LC2h,*LC2l,*LC3h,*LC3l,*CL1h,*CL1l,*CL2h,*CL2l,*CL3h,*CL3l;
    float *CWih,*CWil,*CWhh,*CWhl,*LWih,*LWil,*LWhh,*LWhl,*VW1h,*VW1l,*VW2h,*VW2l;
    SYM(Lh, g_Lh); SYM(Ch, g_Ch);
    SYM(b1L, g_b1L); SYM(b1C, g_b1C); SYM(b2L, g_b2L); SYM(b2C, g_b2C);
    SYM(mlpL, g_mlpL); SYM(mlpC, g_mlpC); SYM(msgL, g_msgL); SYM(msgC, g_msgC);
    SYM(gatesC, g_gatesC); SYM(gatesL, g_gatesL); SYM(partials, g_partials);
    SYM(LC1h, g_LC1h); SYM(LC1l, g_LC1l); SYM(LC2h, g_LC2h); SYM(LC2l, g_LC2l);
    SYM(LC3h, g_LC3h); SYM(LC3l, g_LC3l);
    SYM(CL1h, g_CL1h); SYM(CL1l, g_CL1l); SYM(CL2h, g_CL2h); SYM(CL2l, g_CL2l);
    SYM(CL3h, g_CL3h); SYM(CL3l, g_CL3l);
    SYM(CWih, g_CWih); SYM(CWil, g_CWil); SYM(CWhh, g_CWhh); SYM(CWhl, g_CWhl);
    SYM(LWih, g_LWih); SYM(LWil, g_LWil); SYM(LWhh, g_LWhh); SYM(LWhl, g_LWhl);
    SYM(VW1h, g_VW1h); SYM(VW1l, g_VW1l); SYM(VW2h, g_VW2h); SYM(VW2l, g_VW2l);

    // ---- setup: exactly 3 launches (keeps ncu -s 5 on a GEMM) ----
    build_both_kernel<<<LIT_BLOCKS + CLS_BLOCKS, 256>>>(M);

    WSplitAll ws = {{
        {LC_W1, LC1h, LC1l, H1, E,  E},
        {LC_W2, LC2h, LC2l, H2, H1, H1},
        {LC_W3, LC3h, LC3l, E,  H2, H2P},
        {CL_W1, CL1h, CL1l, H1, E,  E},
        {CL_W2, CL2h, CL2l, H2, H1, H1},
        {CL_W3, CL3h, CL3l, E,  H2, H2P},
        {C_Wih, CWih, CWil, NG, E,  E},
        {C_Whh, CWhh, CWhl, NG, E,  E},
        {L_Wih, LWih, LWil, NG, E,  E},
        {L_Whh, LWhh, LWhl, NG, E,  E},
        {V_W1,  VW1h, VW1l, H1, E,  E},
        {V_W2,  VW2h, VW2l, H2, H1, H1},
    }};
    dim3 sg((H2 * H1 + 255) / 256, 12);
    split_all_kernel<<<sg, 256>>>(ws);

    init_states_kernel<<<((NLITS + NCLS) * E + 255) / 256, 256>>>(L_init, C_init);

    GP dummy = {};

    for (int t = 0; t < TSTEPS; t++) {
        // MLP layer 1: lits use LC weights, clauses use CL weights
        GP a1 = {{Lh}, {LC1h}, {LC1l}, LC_b1, b1L, NLITS, 1};
        GP b1 = {{Ch}, {CL1h}, {CL1l}, CL_b1, b1C, NCLS, 1};
        launch_gemm<true>(a1, b1, 2, H1, E, H1);

        // MLP layer 2 (K=400)
        GP a2 = {{b1L}, {LC2h}, {LC2l}, LC_b2, b2L, NLITS, 1};
        GP b2 = {{b1C}, {CL2h}, {CL2l}, CL_b2, b2C, NCLS, 1};
        launch_gemm<true>(a2, b2, 2, H2, H1, H2P);

        // MLP layer 3 (no relu; K padded to 208, pad cols of b2 are static zeros)
        GP a3 = {{b2L}, {LC3h}, {LC3l}, LC_b3, mlpL, NLITS, 1};
        GP b3 = {{b2C}, {CL3h}, {CL3l}, CL_b3, mlpC, NCLS, 1};
        launch_gemm<false>(a3, b3, 2, E, H2P, E);

        // sparse aggregation (both directions, one launch)
        spmm_both_kernel<<<(NCLS + NLITS + 7) / 8, 256>>>();

        // LSTM gates: msgs@Wih^T + h@Whh^T + b (pre-update h)
        GP ga = {{msgC, Ch}, {CWih, CWhh}, {CWil, CWhl}, C_b, gatesC, NCLS, 2};
        GP gb = {{msgL, Lh}, {LWih, LWhh}, {LWil, LWhl}, L_b, gatesL, NLITS, 2};
        launch_gemm<false>(ga, gb, 2, NG, E, NG);

        // pointwise state update
        lstm_pointwise_both<<<((NCLS + NLITS) * E + 255) / 256, 256>>>();
    }

    // final vote MLP + mean + logit
    GP v1 = {{Lh}, {VW1h}, {VW1l}, V_b1, b1L, NLITS, 1};
    launch_gemm<true>(v1, dummy, 1, H1, E, H1);
    GP v2 = {{b1L}, {VW2h}, {VW2l}, V_b2, b2L, NLITS, 1};
    launch_gemm<true>(v2, dummy, 1, H2, H1, H2P);
    vote_partial_kernel<<<VOTE_BLOCKS, 256>>>(b2L, V_W3, V_b3, partials);
    finalize_kernel<<<1, 512>>>(partials, VOTE_BLOCKS, out);
}